// round 4
// baseline (speedup 1.0000x reference)
#include <cuda_runtime.h>
#include <cuda_bf16.h>
#include <math.h>
#include <stdint.h>

#define EMB   128
#define NUv   100000
#define NVv   50000
#define NEv   500000

#define WP_STRIDE 264   // words per (kt,tig) W row: 128 cols * 2 (b0,b1 pair) + 8 pad -> conflict-free LDS.64
#define XS_STRIDE 132   // words per X row: 128 + 4 pad -> conflict-free scalar A-frag LDS

// ---------------- scratch (device globals: allocation-guard-safe) ----------
__device__ float g_vt[(size_t)NUv * EMB];
__device__ float g_et[(size_t)NEv * EMB];
__device__ float g_ct[(size_t)NVv * EMB];
__device__ float g_agg[(size_t)NUv * EMB];

// ---------------- tf32 helpers ----------------
__device__ __forceinline__ uint32_t f2tf(float x) {
    uint32_t r;
    asm("cvt.rna.tf32.f32 %0, %1;" : "=r"(r) : "f"(x));
    return r;
}

__device__ __forceinline__ void mma8(float& c0, float& c1, float& c2, float& c3,
                                     uint32_t a0, uint32_t a1, uint32_t a2, uint32_t a3,
                                     uint32_t b0, uint32_t b1)
{
    asm volatile(
        "mma.sync.aligned.m16n8k8.row.col.f32.tf32.tf32.f32 "
        "{%0,%1,%2,%3}, {%4,%5,%6,%7}, {%8,%9}, {%0,%1,%2,%3};"
        : "+f"(c0), "+f"(c1), "+f"(c2), "+f"(c3)
        : "r"(a0), "r"(a1), "r"(a2), "r"(a3), "r"(b0), "r"(b1));
}

// Stage W[128][128] (row-major, [k][n]) into paired-tf32 smem layout:
//   Wp[(kt*4+tig)*WP_STRIDE + 2*n + half]  with k = kt*8 + half*4 + tig
// so (b0,b1) for an (kt,tig,n) is one aligned 8-byte LDS.
__device__ __forceinline__ void stage_W_tf32(const float* __restrict__ W,
                                             uint32_t* __restrict__ Wp, int tid)
{
    #pragma unroll 4
    for (int i = tid; i < EMB * EMB / 4; i += 128) {
        const int k = i >> 5;           // (i*4)/128
        const int n = (i * 4) & 127;
        const float4 w = ((const float4*)W)[i];
        const int kt = k >> 3, kl = k & 7;
        const int tig = kl & 3, half = kl >> 2;
        uint32_t* dst = Wp + (kt * 4 + tig) * WP_STRIDE + 2 * n + half;
        dst[0] = f2tf(w.x);
        dst[2] = f2tf(w.y);
        dst[4] = f2tf(w.z);
        dst[6] = f2tf(w.w);
    }
}

// Mainloop: warp computes rows [r0, r0+16) x all 128 cols. Xs holds tf32 bits.
__device__ __forceinline__ void mma_mainloop(const uint32_t* __restrict__ Xs,
                                             const uint32_t* __restrict__ Wp,
                                             int r0, int gq, int tig,
                                             float acc[16][4])
{
    for (int kt = 0; kt < 16; ++kt) {
        const uint32_t* xl = Xs + (r0 + gq) * XS_STRIDE + kt * 8;
        const uint32_t* xh = Xs + (r0 + gq + 8) * XS_STRIDE + kt * 8;
        const uint32_t a0 = xl[tig];
        const uint32_t a1 = xh[tig];
        const uint32_t a2 = xl[tig + 4];
        const uint32_t a3 = xh[tig + 4];
        const uint32_t* wrow = Wp + (kt * 4 + tig) * WP_STRIDE;
        #pragma unroll
        for (int nt = 0; nt < 16; ++nt) {
            const uint2 b = *(const uint2*)(wrow + 2 * (nt * 8 + gq));
            mma8(acc[nt][0], acc[nt][1], acc[nt][2], acc[nt][3],
                 a0, a1, a2, a3, b.x, b.y);
        }
    }
}

// =====================================================================
// Kernel 1 (tf32): Y[row] = LN(X[row]; g,b) @ W (+bias)
// block = 128 threads (4 warps), 64 rows; warp w -> rows w*16..w*16+15
// =====================================================================
__global__ __launch_bounds__(128)
void ln_gemm_tf32(const float* __restrict__ X, const float* __restrict__ W,
                  const float* __restrict__ bias,
                  const float* __restrict__ g, const float* __restrict__ b,
                  float* __restrict__ Y, int N)
{
    extern __shared__ uint32_t smu[];
    uint32_t* Wp = smu;                       // 64 * 264 words
    uint32_t* Xs = smu + 64 * WP_STRIDE;      // 64 * 132 words
    float*    Xf = (float*)Xs;

    const int tid  = threadIdx.x;
    const int lane = tid & 31;
    const int warp = tid >> 5;
    const int gq   = lane >> 2;
    const int tig  = lane & 3;

    stage_W_tf32(W, Wp, tid);

    const int row0 = blockIdx.x * 64;
    const int r0   = warp * 16;

    const float4 gv = ((const float4*)g)[lane];
    const float4 bv = ((const float4*)b)[lane];

    // stage rows: load + LN + tf32-convert
    #pragma unroll 4
    for (int r = 0; r < 16; ++r) {
        const int row = row0 + r0 + r;
        float4 xv = make_float4(0.f, 0.f, 0.f, 0.f);
        if (row < N) xv = ((const float4*)(X + (size_t)row * EMB))[lane];
        float s  = xv.x + xv.y + xv.z + xv.w;
        float ss = xv.x * xv.x + xv.y * xv.y + xv.z * xv.z + xv.w * xv.w;
        #pragma unroll
        for (int o = 16; o; o >>= 1) {
            s  += __shfl_xor_sync(0xffffffffu, s,  o);
            ss += __shfl_xor_sync(0xffffffffu, ss, o);
        }
        const float mu   = s * (1.f / EMB);
        const float rstd = rsqrtf(ss * (1.f / EMB) - mu * mu + 1e-5f);
        uint32_t* d = Xs + (r0 + r) * XS_STRIDE + lane * 4;
        d[0] = f2tf((xv.x - mu) * rstd * gv.x + bv.x);
        d[1] = f2tf((xv.y - mu) * rstd * gv.y + bv.y);
        d[2] = f2tf((xv.z - mu) * rstd * gv.z + bv.z);
        d[3] = f2tf((xv.w - mu) * rstd * gv.w + bv.w);
    }
    __syncthreads();

    float acc[16][4];
    #pragma unroll
    for (int i = 0; i < 16; ++i)
        #pragma unroll
        for (int j = 0; j < 4; ++j) acc[i][j] = 0.f;

    mma_mainloop(Xs, Wp, r0, gq, tig, acc);

    // epilogue: repack through (now-free, warp-private) Xs rows for coalesced stores
    __syncwarp();
    #pragma unroll
    for (int nt = 0; nt < 16; ++nt) {
        float* rl = Xf + (r0 + gq)     * XS_STRIDE + nt * 8 + 2 * tig;
        float* rh = Xf + (r0 + gq + 8) * XS_STRIDE + nt * 8 + 2 * tig;
        rl[0] = acc[nt][0]; rl[1] = acc[nt][1];
        rh[0] = acc[nt][2]; rh[1] = acc[nt][3];
    }
    __syncwarp();

    float4 bb = make_float4(0.f, 0.f, 0.f, 0.f);
    if (bias) bb = ((const float4*)bias)[lane];
    #pragma unroll 4
    for (int r = 0; r < 16; ++r) {
        const int row = row0 + r0 + r;
        if (row < N) {
            float4 o = ((const float4*)(Xf + (r0 + r) * XS_STRIDE))[lane];
            o.x += bb.x; o.y += bb.y; o.z += bb.z; o.w += bb.w;
            ((float4*)(Y + (size_t)row * EMB))[lane] = o;
        }
    }
}

// =====================================================================
// Kernel 2 (tf32): fused edge join + LN + GEMM + LN + atomic scatter
// block = 128 threads (4 warps), 64 edges; warp w -> edges w*16..w*16+15
// =====================================================================
__global__ __launch_bounds__(128)
void edge_join_tf32(const float* __restrict__ vt, const float* __restrict__ et,
                    const float* __restrict__ ct,
                    const int* __restrict__ e_u, const int* __restrict__ e_v,
                    const float* __restrict__ Wj, const float* __restrict__ bj,
                    const float* __restrict__ g1, const float* __restrict__ b1,
                    const float* __restrict__ g2, const float* __restrict__ b2,
                    float* __restrict__ agg, int seg_by_ev, int NE)
{
    extern __shared__ uint32_t smu[];
    uint32_t* Wp = smu;
    uint32_t* Xs = smu + 64 * WP_STRIDE;
    float*    Xf = (float*)Xs;
    __shared__ int segs[64];

    const int tid  = threadIdx.x;
    const int lane = tid & 31;
    const int warp = tid >> 5;
    const int gq   = lane >> 2;
    const int tig  = lane & 3;

    stage_W_tf32(Wj, Wp, tid);

    const int e0 = blockIdx.x * 64;
    const int r0 = warp * 16;

    // phase 1: gather + relu (pure MLP, no reductions in the way)
    #pragma unroll 4
    for (int r = 0; r < 16; ++r) {
        const int e = e0 + r0 + r;
        float4 xv = make_float4(0.f, 0.f, 0.f, 0.f);
        if (e < NE) {
            const int iu = __ldg(e_u + e);
            const int iv = __ldg(e_v + e);
            if (lane == 0) segs[r0 + r] = seg_by_ev ? iv : iu;
            const float4 a = ((const float4*)(vt + (size_t)iu * EMB))[lane];
            const float4 m = ((const float4*)(et + (size_t)e  * EMB))[lane];
            const float4 c = ((const float4*)(ct + (size_t)iv * EMB))[lane];
            xv.x = fmaxf(a.x + m.x + c.x, 0.f);
            xv.y = fmaxf(a.y + m.y + c.y, 0.f);
            xv.z = fmaxf(a.z + m.z + c.z, 0.f);
            xv.w = fmaxf(a.w + m.w + c.w, 0.f);
        } else if (lane == 0) {
            segs[r0 + r] = -1;
        }
        ((float4*)(Xf + (r0 + r) * XS_STRIDE))[lane] = xv;
    }
    __syncwarp();

    // phase 2: LN + tf32 convert (in place)
    const float4 g1v = ((const float4*)g1)[lane];
    const float4 b1v = ((const float4*)b1)[lane];
    #pragma unroll 4
    for (int r = 0; r < 16; ++r) {
        const float4 xv = ((const float4*)(Xf + (r0 + r) * XS_STRIDE))[lane];
        float s  = xv.x + xv.y + xv.z + xv.w;
        float ss = xv.x * xv.x + xv.y * xv.y + xv.z * xv.z + xv.w * xv.w;
        #pragma unroll
        for (int o = 16; o; o >>= 1) {
            s  += __shfl_xor_sync(0xffffffffu, s,  o);
            ss += __shfl_xor_sync(0xffffffffu, ss, o);
        }
        const float mu   = s * (1.f / EMB);
        const float rstd = rsqrtf(ss * (1.f / EMB) - mu * mu + 1e-5f);
        uint32_t* d = Xs + (r0 + r) * XS_STRIDE + lane * 4;
        d[0] = f2tf((xv.x - mu) * rstd * g1v.x + b1v.x);
        d[1] = f2tf((xv.y - mu) * rstd * g1v.y + b1v.y);
        d[2] = f2tf((xv.z - mu) * rstd * g1v.z + b1v.z);
        d[3] = f2tf((xv.w - mu) * rstd * g1v.w + b1v.w);
    }
    __syncthreads();

    float acc[16][4];
    #pragma unroll
    for (int i = 0; i < 16; ++i)
        #pragma unroll
        for (int j = 0; j < 4; ++j) acc[i][j] = 0.f;

    mma_mainloop(Xs, Wp, r0, gq, tig, acc);

    // epilogue: +bias, per-row LN (rows gq and gq+8, quad-local), atomic scatter
    float s_lo = 0.f, ss_lo = 0.f, s_hi = 0.f, ss_hi = 0.f;
    #pragma unroll
    for (int nt = 0; nt < 16; ++nt) {
        const int col = nt * 8 + 2 * tig;
        const float bj0 = __ldg(bj + col), bj1 = __ldg(bj + col + 1);
        acc[nt][0] += bj0; acc[nt][1] += bj1;
        acc[nt][2] += bj0; acc[nt][3] += bj1;
        s_lo  += acc[nt][0] + acc[nt][1];
        ss_lo += acc[nt][0] * acc[nt][0] + acc[nt][1] * acc[nt][1];
        s_hi  += acc[nt][2] + acc[nt][3];
        ss_hi += acc[nt][2] * acc[nt][2] + acc[nt][3] * acc[nt][3];
    }
    #pragma unroll
    for (int o = 1; o < 4; o <<= 1) {
        s_lo  += __shfl_xor_sync(0xffffffffu, s_lo,  o);
        ss_lo += __shfl_xor_sync(0xffffffffu, ss_lo, o);
        s_hi  += __shfl_xor_sync(0xffffffffu, s_hi,  o);
        ss_hi += __shfl_xor_sync(0xffffffffu, ss_hi, o);
    }
    const float mu_lo   = s_lo * (1.f / EMB);
    const float rstd_lo = rsqrtf(ss_lo * (1.f / EMB) - mu_lo * mu_lo + 1e-5f);
    const float mu_hi   = s_hi * (1.f / EMB);
    const float rstd_hi = rsqrtf(ss_hi * (1.f / EMB) - mu_hi * mu_hi + 1e-5f);

    const int seg_lo = segs[r0 + gq];
    const int seg_hi = segs[r0 + gq + 8];
    float* base_lo = agg + (size_t)(seg_lo < 0 ? 0 : seg_lo) * EMB;
    float* base_hi = agg + (size_t)(seg_hi < 0 ? 0 : seg_hi) * EMB;

    #pragma unroll
    for (int nt = 0; nt < 16; ++nt) {
        const int col = nt * 8 + 2 * tig;
        const float g20 = __ldg(g2 + col), g21 = __ldg(g2 + col + 1);
        const float b20 = __ldg(b2 + col), b21 = __ldg(b2 + col + 1);
        if (seg_lo >= 0) {
            atomicAdd(base_lo + col,     (acc[nt][0] - mu_lo) * rstd_lo * g20 + b20);
            atomicAdd(base_lo + col + 1, (acc[nt][1] - mu_lo) * rstd_lo * g21 + b21);
        }
        if (seg_hi >= 0) {
            atomicAdd(base_hi + col,     (acc[nt][2] - mu_hi) * rstd_hi * g20 + b20);
            atomicAdd(base_hi + col + 1, (acc[nt][3] - mu_hi) * rstd_hi * g21 + b21);
        }
    }
}

// =====================================================================
// Kernel 3: merge (unchanged fp32 FFMA):
//   out = LN(relu(concat([h, agg]) @ W_merge + b_merge)); dst = h + out
// =====================================================================
__global__ __launch_bounds__(256, 1)
void merge_kernel(const float* __restrict__ h, const float* __restrict__ agg,
                  const float* __restrict__ Wm, const float* __restrict__ bm,
                  const float* __restrict__ gm, const float* __restrict__ bmln,
                  float* __restrict__ dst, int N)
{
    extern __shared__ float sm[];
    float* Ws = sm;                    // 256*128
    float* Xsm = sm + 2 * EMB * EMB;   // 64*256

    const int tid  = threadIdx.x;
    const int lane = tid & 31;
    const int warp = tid >> 5;

    {
        const float4* W4  = (const float4*)Wm;
        float4*       Ws4 = (float4*)Ws;
        #pragma unroll
        for (int i = tid; i < 2 * EMB * EMB / 4; i += 256) Ws4[i] = W4[i];
    }

    const int row0 = blockIdx.x * 64;
    #pragma unroll
    for (int r = 0; r < 8; r++) {
        const int row = row0 + warp * 8 + r;
        float4 hv = make_float4(0.f, 0.f, 0.f, 0.f);
        float4 av = make_float4(0.f, 0.f, 0.f, 0.f);
        if (row < N) {
            hv = ((const float4*)(h   + (size_t)row * EMB))[lane];
            av = ((const float4*)(agg + (size_t)row * EMB))[lane];
        }
        ((float4*)(Xsm + (warp * 8 + r) * 256))[lane]       = hv;
        ((float4*)(Xsm + (warp * 8 + r) * 256 + EMB))[lane] = av;
    }
    __syncthreads();

    float acc[8][4];
    #pragma unroll
    for (int r = 0; r < 8; r++)
        #pragma unroll
        for (int i = 0; i < 4; i++) acc[r][i] = 0.f;

    for (int k = 0; k < 256; k += 4) {
        float4 xr[8];
        #pragma unroll
        for (int r = 0; r < 8; r++)
            xr[r] = *(const float4*)(Xsm + (warp * 8 + r) * 256 + k);
        #pragma unroll
        for (int kk = 0; kk < 4; kk++) {
            const float4 wv = ((const float4*)(Ws + (k + kk) * EMB))[lane];
            #pragma unroll
            for (int r = 0; r < 8; r++) {
                const float xk = (kk == 0) ? xr[r].x : (kk == 1) ? xr[r].y
                               : (kk == 2) ? xr[r].z : xr[r].w;
                acc[r][0] += xk * wv.x; acc[r][1] += xk * wv.y;
                acc[r][2] += xk * wv.z; acc[r][3] += xk * wv.w;
            }
        }
    }

    const float4 bmv  = ((const float4*)bm)[lane];
    const float4 gmv  = ((const float4*)gm)[lane];
    const float4 blnv = ((const float4*)bmln)[lane];

    #pragma unroll
    for (int r = 0; r < 8; r++) {
        float y0 = fmaxf(acc[r][0] + bmv.x, 0.f);
        float y1 = fmaxf(acc[r][1] + bmv.y, 0.f);
        float y2 = fmaxf(acc[r][2] + bmv.z, 0.f);
        float y3 = fmaxf(acc[r][3] + bmv.w, 0.f);
        float s  = y0 + y1 + y2 + y3;
        float ss = y0*y0 + y1*y1 + y2*y2 + y3*y3;
        #pragma unroll
        for (int o = 16; o; o >>= 1) {
            s  += __shfl_xor_sync(0xffffffffu, s,  o);
            ss += __shfl_xor_sync(0xffffffffu, ss, o);
        }
        const float mu   = s * (1.f / EMB);
        const float rstd = rsqrtf(ss * (1.f / EMB) - mu * mu + 1e-5f);
        const int row = row0 + warp * 8 + r;
        if (row < N) {
            const float4 hv = ((const float4*)(Xsm + (warp * 8 + r) * 256))[lane];
            float4 o;
            o.x = hv.x + ((y0 - mu) * rstd * gmv.x + blnv.x);
            o.y = hv.y + ((y1 - mu) * rstd * gmv.y + blnv.y);
            o.z = hv.z + ((y2 - mu) * rstd * gmv.z + blnv.z);
            o.w = hv.w + ((y3 - mu) * rstd * gmv.w + blnv.w);
            ((float4*)(dst + (size_t)row * EMB))[lane] = o;
        }
    }
}

// =====================================================================
// host
// =====================================================================
extern "C" void kernel_launch(void* const* d_in, const int* in_sizes, int n_in,
                              void* d_out, int out_size)
{
    const float* variable_emb   = (const float*)d_in[0];
    const float* edge_emb       = (const float*)d_in[1];
    const float* constraint_emb = (const float*)d_in[2];
    const int*   e_u            = (const int*)  d_in[3];
    const int*   e_v            = (const int*)  d_in[4];
    const float* W_left   = (const float*)d_in[5];
    const float* b_left   = (const float*)d_in[6];
    const float* W_edge   = (const float*)d_in[7];
    const float* W_right  = (const float*)d_in[8];
    const float* W_join   = (const float*)d_in[9];
    const float* b_join   = (const float*)d_in[10];
    const float* W_merge  = (const float*)d_in[11];
    const float* b_merge  = (const float*)d_in[12];
    const float* g_var    = (const float*)d_in[13];
    const float* b_var    = (const float*)d_in[14];
    const float* g_edge   = (const float*)d_in[15];
    const float* b_edge   = (const float*)d_in[16];
    const float* g_con    = (const float*)d_in[17];
    const float* b_con    = (const float*)d_in[18];
    const float* g_join_ln  = (const float*)d_in[19];
    const float* b_join_ln  = (const float*)d_in[20];
    const float* g_joint    = (const float*)d_in[21];
    const float* b_joint    = (const float*)d_in[22];
    const float* g_merge    = (const float*)d_in[23];
    const float* b_merge_ln = (const float*)d_in[24];

    float* out_var = (float*)d_out;
    float* out_con = (float*)d_out + (size_t)NUv * EMB;

    float *vt, *et, *ct, *agg;
    cudaGetSymbolAddress((void**)&vt,  g_vt);
    cudaGetSymbolAddress((void**)&et,  g_et);
    cudaGetSymbolAddress((void**)&ct,  g_ct);
    cudaGetSymbolAddress((void**)&agg, g_agg);

    const int SM_MMA   = (64 * WP_STRIDE + 64 * XS_STRIDE) * 4;        // 101,376 B
    const int SM_MERGE = (2 * EMB * EMB + 64 * 256) * sizeof(float);   // 192 KB

    cudaFuncSetAttribute(ln_gemm_tf32,   cudaFuncAttributeMaxDynamicSharedMemorySize, SM_MMA);
    cudaFuncSetAttribute(edge_join_tf32, cudaFuncAttributeMaxDynamicSharedMemorySize, SM_MMA);
    cudaFuncSetAttribute(merge_kernel,   cudaFuncAttributeMaxDynamicSharedMemorySize, SM_MERGE);

    const dim3 blk128(128);
    const dim3 blk256(256);
    const int gb_u = (NUv + 63) / 64;
    const int gb_v = (NVv + 63) / 64;
    const int gb_e = (NEv + 63) / 64;

    // shared pre-transforms (vt and et identical in both passes)
    ln_gemm_tf32<<<gb_u, blk128, SM_MMA>>>(variable_emb, W_left, b_left, g_var, b_var, vt, NUv);
    ln_gemm_tf32<<<gb_e, blk128, SM_MMA>>>(edge_emb, W_edge, nullptr, g_edge, b_edge, et, NEv);
    ln_gemm_tf32<<<gb_v, blk128, SM_MMA>>>(constraint_emb, W_right, nullptr, g_con, b_con, ct, NVv);

    // ---------------- pass 1: var -> con ----------------
    cudaMemsetAsync(agg, 0, (size_t)NVv * EMB * sizeof(float), 0);
    edge_join_tf32<<<gb_e, blk128, SM_MMA>>>(vt, et, ct, e_u, e_v, W_join, b_join,
                                             g_join_ln, b_join_ln, g_joint, b_joint,
                                             agg, /*seg_by_ev=*/1, NEv);
    merge_kernel<<<gb_v, blk256, SM_MERGE>>>(ct, agg, W_merge, b_merge, g_merge, b_merge_ln,
                                             out_con, NVv);

    // ---------------- pass 2: con -> var ----------------
    ln_gemm_tf32<<<gb_v, blk128, SM_MMA>>>(out_con, W_right, nullptr, g_con, b_con, ct, NVv);
    cudaMemsetAsync(agg, 0, (size_t)NUv * EMB * sizeof(float), 0);
    edge_join_tf32<<<gb_e, blk128, SM_MMA>>>(vt, et, ct, e_u, e_v, W_join, b_join,
                                             g_join_ln, b_join_ln, g_joint, b_joint,
                                             agg, /*seg_by_ev=*/0, NEv);
    merge_kernel<<<gb_u, blk256, SM_MERGE>>>(vt, agg, W_merge, b_merge, g_merge, b_merge_ln,
                                             out_var, NUv);
}

// round 5
// speedup vs baseline: 1.6109x; 1.6109x over previous
#include <cuda_runtime.h>
#include <cuda_bf16.h>
#include <math.h>
#include <stdint.h>

#define EMB   128
#define NUv   100000
#define NVv   50000
#define NEv   500000

#define WP_STRIDE 264   // words per (kt,tig) W row (paired b0,b1) -> conflict-free LDS.64
#define XS_STRIDE 132   // words per X row -> conflict-free A-frag LDS

// ---------------- scratch (device globals: allocation-guard-safe) ----------
__device__ float g_vt[(size_t)NUv * EMB];
__device__ float g_et[(size_t)NEv * EMB];
__device__ float g_ct[(size_t)NVv * EMB];
__device__ float g_agg[(size_t)NUv * EMB];

// ---------------- tf32 helpers ----------------
__device__ __forceinline__ uint32_t f2tf(float x) {
    uint32_t r;
    asm("cvt.rna.tf32.f32 %0, %1;" : "=r"(r) : "f"(x));
    return r;
}

__device__ __forceinline__ void mma8(float& c0, float& c1, float& c2, float& c3,
                                     uint32_t a0, uint32_t a1, uint32_t a2, uint32_t a3,
                                     uint32_t b0, uint32_t b1)
{
    asm volatile(
        "mma.sync.aligned.m16n8k8.row.col.f32.tf32.tf32.f32 "
        "{%0,%1,%2,%3}, {%4,%5,%6,%7}, {%8,%9}, {%0,%1,%2,%3};"
        : "+f"(c0), "+f"(c1), "+f"(c2), "+f"(c3)
        : "r"(a0), "r"(a1), "r"(a2), "r"(a3), "r"(b0), "r"(b1));
}

__device__ __forceinline__ void red_v4(float* p, float v0, float v1, float v2, float v3)
{
    asm volatile("red.global.add.v4.f32 [%0], {%1,%2,%3,%4};"
                 :: "l"(p), "f"(v0), "f"(v1), "f"(v2), "f"(v3) : "memory");
}

// Stage W[128][128] ([k][n] row-major) into paired-tf32 smem:
//   Wp[(kt*4+tig)*WP_STRIDE + 2*n + half], k = kt*8 + half*4 + tig
__device__ __forceinline__ void stage_W_tf32(const float* __restrict__ W,
                                             uint32_t* __restrict__ Wp,
                                             int tid, int nthreads)
{
    #pragma unroll 4
    for (int i = tid; i < EMB * EMB / 4; i += nthreads) {
        const int k = i >> 5;
        const int n = (i * 4) & 127;
        const float4 w = ((const float4*)W)[i];
        const int kt = k >> 3, kl = k & 7;
        const int tig = kl & 3, half = kl >> 2;
        uint32_t* dst = Wp + (kt * 4 + tig) * WP_STRIDE + 2 * n + half;
        dst[0] = f2tf(w.x);
        dst[2] = f2tf(w.y);
        dst[4] = f2tf(w.z);
        dst[6] = f2tf(w.w);
    }
}

// Warp mainloop over HALF the N dim: rows [r0, r0+16), cols [ch*64, ch*64+64)
__device__ __forceinline__ void mma_mainloop_half(const uint32_t* __restrict__ Xs,
                                                  const uint32_t* __restrict__ Wp,
                                                  int r0, int gq, int tig, int ch,
                                                  float acc[8][4])
{
    #pragma unroll
    for (int kt = 0; kt < 16; ++kt) {
        const uint32_t* xl = Xs + (r0 + gq) * XS_STRIDE + kt * 8;
        const uint32_t* xh = Xs + (r0 + gq + 8) * XS_STRIDE + kt * 8;
        const uint32_t a0 = xl[tig];
        const uint32_t a1 = xh[tig];
        const uint32_t a2 = xl[tig + 4];
        const uint32_t a3 = xh[tig + 4];
        const uint32_t* wrow = Wp + (kt * 4 + tig) * WP_STRIDE + 2 * (ch * 64);
        #pragma unroll
        for (int nt = 0; nt < 8; ++nt) {
            const uint2 b = *(const uint2*)(wrow + 2 * (nt * 8 + gq));
            mma8(acc[nt][0], acc[nt][1], acc[nt][2], acc[nt][3],
                 a0, a1, a2, a3, b.x, b.y);
        }
    }
}

// =====================================================================
// Kernel 1 (tf32): Y[row] = LN(X[row]; g,b) @ W (+bias)
// block = 256 threads (8 warps), tile 64 rows.
// phase1: warp w stages rows w*8..w*8+7. mainloop: warp w -> rows
// (w>>1)*16..+16, col half (w&1).
// =====================================================================
__global__ __launch_bounds__(256)
void ln_gemm_tf32(const float* __restrict__ X, const float* __restrict__ W,
                  const float* __restrict__ bias,
                  const float* __restrict__ g, const float* __restrict__ b,
                  float* __restrict__ Y, int N)
{
    extern __shared__ uint32_t smu[];
    uint32_t* Wp = smu;                       // 64*264 words
    uint32_t* Xs = smu + 64 * WP_STRIDE;      // 64*132 words
    float*    Xf = (float*)Xs;

    const int tid  = threadIdx.x;
    const int lane = tid & 31;
    const int warp = tid >> 5;
    const int gq   = lane >> 2;
    const int tig  = lane & 3;
    const int r0   = (warp >> 1) * 16;
    const int ch   = warp & 1;

    stage_W_tf32(W, Wp, tid, 256);

    const int row0 = blockIdx.x * 64;

    const float4 gv = ((const float4*)g)[lane];
    const float4 bv = ((const float4*)b)[lane];

    // stage + LN + tf32 convert: warp w -> 8 rows
    #pragma unroll
    for (int r = 0; r < 8; ++r) {
        const int lr  = warp * 8 + r;
        const int row = row0 + lr;
        float4 xv = make_float4(0.f, 0.f, 0.f, 0.f);
        if (row < N) xv = ((const float4*)(X + (size_t)row * EMB))[lane];
        float s  = xv.x + xv.y + xv.z + xv.w;
        float ss = xv.x * xv.x + xv.y * xv.y + xv.z * xv.z + xv.w * xv.w;
        #pragma unroll
        for (int o = 16; o; o >>= 1) {
            s  += __shfl_xor_sync(0xffffffffu, s,  o);
            ss += __shfl_xor_sync(0xffffffffu, ss, o);
        }
        const float mu   = s * (1.f / EMB);
        const float rstd = rsqrtf(ss * (1.f / EMB) - mu * mu + 1e-5f);
        uint32_t* d = Xs + lr * XS_STRIDE + lane * 4;
        d[0] = f2tf((xv.x - mu) * rstd * gv.x + bv.x);
        d[1] = f2tf((xv.y - mu) * rstd * gv.y + bv.y);
        d[2] = f2tf((xv.z - mu) * rstd * gv.z + bv.z);
        d[3] = f2tf((xv.w - mu) * rstd * gv.w + bv.w);
    }
    __syncthreads();

    float acc[8][4];
    #pragma unroll
    for (int i = 0; i < 8; ++i)
        #pragma unroll
        for (int j = 0; j < 4; ++j) acc[i][j] = 0.f;

    mma_mainloop_half(Xs, Wp, r0, gq, tig, ch, acc);

    // repack through Xs for coalesced stores
    __syncthreads();
    #pragma unroll
    for (int nt = 0; nt < 8; ++nt) {
        const int col = ch * 64 + nt * 8 + 2 * tig;
        float* rl = Xf + (r0 + gq)     * XS_STRIDE + col;
        float* rh = Xf + (r0 + gq + 8) * XS_STRIDE + col;
        rl[0] = acc[nt][0]; rl[1] = acc[nt][1];
        rh[0] = acc[nt][2]; rh[1] = acc[nt][3];
    }
    __syncthreads();

    float4 bb = make_float4(0.f, 0.f, 0.f, 0.f);
    if (bias) bb = ((const float4*)bias)[lane];
    #pragma unroll
    for (int r = 0; r < 8; ++r) {
        const int lr  = warp * 8 + r;
        const int row = row0 + lr;
        if (row < N) {
            float4 o = ((const float4*)(Xf + lr * XS_STRIDE))[lane];
            o.x += bb.x; o.y += bb.y; o.z += bb.z; o.w += bb.w;
            ((float4*)(Y + (size_t)row * EMB))[lane] = o;
        }
    }
}

// =====================================================================
// Kernel 2 (tf32): fused edge join + LN + GEMM + LN + vec4 red scatter
// block = 256 threads (8 warps), 64 edges.
// =====================================================================
__global__ __launch_bounds__(256)
void edge_join_tf32(const float* __restrict__ vt, const float* __restrict__ et,
                    const float* __restrict__ ct,
                    const int* __restrict__ e_u, const int* __restrict__ e_v,
                    const float* __restrict__ Wj, const float* __restrict__ bj,
                    const float* __restrict__ g1, const float* __restrict__ b1,
                    const float* __restrict__ g2, const float* __restrict__ b2,
                    float* __restrict__ agg, int seg_by_ev, int NE)
{
    extern __shared__ uint32_t smu[];
    uint32_t* Wp = smu;
    uint32_t* Xs = smu + 64 * WP_STRIDE;
    __shared__ int   segs[64];
    __shared__ float sP[64][2], ssP[64][2];

    const int tid  = threadIdx.x;
    const int lane = tid & 31;
    const int warp = tid >> 5;
    const int gq   = lane >> 2;
    const int tig  = lane & 3;
    const int r0   = (warp >> 1) * 16;
    const int ch   = warp & 1;

    stage_W_tf32(Wj, Wp, tid, 256);

    const int e0 = blockIdx.x * 64;
    const float4 g1v = ((const float4*)g1)[lane];
    const float4 b1v = ((const float4*)b1)[lane];

    // gather + relu + LN + tf32 convert: warp w -> 8 edges
    #pragma unroll
    for (int r = 0; r < 8; ++r) {
        const int lr = warp * 8 + r;
        const int e  = e0 + lr;
        float4 xv = make_float4(0.f, 0.f, 0.f, 0.f);
        if (e < NE) {
            const int iu = __ldg(e_u + e);
            const int iv = __ldg(e_v + e);
            if (lane == 0) segs[lr] = seg_by_ev ? iv : iu;
            const float4 a = ((const float4*)(vt + (size_t)iu * EMB))[lane];
            const float4 m = ((const float4*)(et + (size_t)e  * EMB))[lane];
            const float4 c = ((const float4*)(ct + (size_t)iv * EMB))[lane];
            xv.x = fmaxf(a.x + m.x + c.x, 0.f);
            xv.y = fmaxf(a.y + m.y + c.y, 0.f);
            xv.z = fmaxf(a.z + m.z + c.z, 0.f);
            xv.w = fmaxf(a.w + m.w + c.w, 0.f);
        } else if (lane == 0) {
            segs[lr] = -1;
        }
        float s  = xv.x + xv.y + xv.z + xv.w;
        float ss = xv.x * xv.x + xv.y * xv.y + xv.z * xv.z + xv.w * xv.w;
        #pragma unroll
        for (int o = 16; o; o >>= 1) {
            s  += __shfl_xor_sync(0xffffffffu, s,  o);
            ss += __shfl_xor_sync(0xffffffffu, ss, o);
        }
        const float mu   = s * (1.f / EMB);
        const float rstd = rsqrtf(ss * (1.f / EMB) - mu * mu + 1e-5f);
        uint32_t* d = Xs + lr * XS_STRIDE + lane * 4;
        d[0] = f2tf((xv.x - mu) * rstd * g1v.x + b1v.x);
        d[1] = f2tf((xv.y - mu) * rstd * g1v.y + b1v.y);
        d[2] = f2tf((xv.z - mu) * rstd * g1v.z + b1v.z);
        d[3] = f2tf((xv.w - mu) * rstd * g1v.w + b1v.w);
    }
    __syncthreads();

    float acc[8][4];
    #pragma unroll
    for (int i = 0; i < 8; ++i)
        #pragma unroll
        for (int j = 0; j < 4; ++j) acc[i][j] = 0.f;

    mma_mainloop_half(Xs, Wp, r0, gq, tig, ch, acc);

    // ---- epilogue: +bias, cross-warp LN stats ----
    float s_lo = 0.f, ss_lo = 0.f, s_hi = 0.f, ss_hi = 0.f;
    #pragma unroll
    for (int nt = 0; nt < 8; ++nt) {
        const int col = ch * 64 + nt * 8 + 2 * tig;
        const float2 bjv = *(const float2*)(bj + col);
        acc[nt][0] += bjv.x; acc[nt][1] += bjv.y;
        acc[nt][2] += bjv.x; acc[nt][3] += bjv.y;
        s_lo  += acc[nt][0] + acc[nt][1];
        ss_lo += acc[nt][0] * acc[nt][0] + acc[nt][1] * acc[nt][1];
        s_hi  += acc[nt][2] + acc[nt][3];
        ss_hi += acc[nt][2] * acc[nt][2] + acc[nt][3] * acc[nt][3];
    }
    #pragma unroll
    for (int o = 1; o < 4; o <<= 1) {
        s_lo  += __shfl_xor_sync(0xffffffffu, s_lo,  o);
        ss_lo += __shfl_xor_sync(0xffffffffu, ss_lo, o);
        s_hi  += __shfl_xor_sync(0xffffffffu, s_hi,  o);
        ss_hi += __shfl_xor_sync(0xffffffffu, ss_hi, o);
    }
    if (tig == 0) {
        sP [r0 + gq][ch]     = s_lo;  ssP[r0 + gq][ch]     = ss_lo;
        sP [r0 + gq + 8][ch] = s_hi;  ssP[r0 + gq + 8][ch] = ss_hi;
    }
    __syncthreads();

    const float st_lo  = sP [r0 + gq][0]     + sP [r0 + gq][1];
    const float sst_lo = ssP[r0 + gq][0]     + ssP[r0 + gq][1];
    const float st_hi  = sP [r0 + gq + 8][0] + sP [r0 + gq + 8][1];
    const float sst_hi = ssP[r0 + gq + 8][0] + ssP[r0 + gq + 8][1];
    const float mu_lo   = st_lo * (1.f / EMB);
    const float rstd_lo = rsqrtf(sst_lo * (1.f / EMB) - mu_lo * mu_lo + 1e-5f);
    const float mu_hi   = st_hi * (1.f / EMB);
    const float rstd_hi = rsqrtf(sst_hi * (1.f / EMB) - mu_hi * mu_hi + 1e-5f);

    const int  seg_lo = segs[r0 + gq];
    const int  seg_hi = segs[r0 + gq + 8];
    const bool odd    = (tig & 1);
    const float mu    = odd ? mu_hi   : mu_lo;
    const float rstd  = odd ? rstd_hi : rstd_lo;
    const int   seg   = odd ? seg_hi  : seg_lo;
    float* base = agg + (size_t)(seg < 0 ? 0 : seg) * EMB;

    // repack (2col x 2row) frags -> 4 contiguous cols of one row, red.v4
    #pragma unroll
    for (int nt = 0; nt < 8; ++nt) {
        const float l0 = acc[nt][0], l1 = acc[nt][1];
        const float h0 = acc[nt][2], h1 = acc[nt][3];
        const float p0 = __shfl_xor_sync(0xffffffffu, odd ? l0 : h0, 1);
        const float p1 = __shfl_xor_sync(0xffffffffu, odd ? l1 : h1, 1);
        float v0, v1, v2, v3;
        if (!odd) { v0 = l0; v1 = l1; v2 = p0; v3 = p1; }
        else      { v0 = p0; v1 = p1; v2 = h0; v3 = h1; }
        const int col = ch * 64 + nt * 8 + (tig >> 1) * 4;
        const float4 gg = *(const float4*)(g2 + col);
        const float4 b2v = *(const float4*)(b2 + col);
        v0 = (v0 - mu) * rstd * gg.x + b2v.x;
        v1 = (v1 - mu) * rstd * gg.y + b2v.y;
        v2 = (v2 - mu) * rstd * gg.z + b2v.z;
        v3 = (v3 - mu) * rstd * gg.w + b2v.w;
        if (seg >= 0) red_v4(base + col, v0, v1, v2, v3);
    }
}

// =====================================================================
// Kernel 3: merge (fp32 FFMA):
//   out = LN(relu(concat([h, agg]) @ W_merge + b_merge)); dst = h + out
// =====================================================================
__global__ __launch_bounds__(256, 1)
void merge_kernel(const float* __restrict__ h, const float* __restrict__ agg,
                  const float* __restrict__ Wm, const float* __restrict__ bm,
                  const float* __restrict__ gm, const float* __restrict__ bmln,
                  float* __restrict__ dst, int N)
{
    extern __shared__ float sm[];
    float* Ws  = sm;                   // 256*128
    float* Xsm = sm + 2 * EMB * EMB;   // 64*256

    const int tid  = threadIdx.x;
    const int lane = tid & 31;
    const int warp = tid >> 5;

    {
        const float4* W4  = (const float4*)Wm;
        float4*       Ws4 = (float4*)Ws;
        #pragma unroll
        for (int i = tid; i < 2 * EMB * EMB / 4; i += 256) Ws4[i] = W4[i];
    }

    const int row0 = blockIdx.x * 64;
    #pragma unroll
    for (int r = 0; r < 8; r++) {
        const int row = row0 + warp * 8 + r;
        float4 hv = make_float4(0.f, 0.f, 0.f, 0.f);
        float4 av = make_float4(0.f, 0.f, 0.f, 0.f);
        if (row < N) {
            hv = ((const float4*)(h   + (size_t)row * EMB))[lane];
            av = ((const float4*)(agg + (size_t)row * EMB))[lane];
        }
        ((float4*)(Xsm + (warp * 8 + r) * 256))[lane]       = hv;
        ((float4*)(Xsm + (warp * 8 + r) * 256 + EMB))[lane] = av;
    }
    __syncthreads();

    float acc[8][4];
    #pragma unroll
    for (int r = 0; r < 8; r++)
        #pragma unroll
        for (int i = 0; i < 4; i++) acc[r][i] = 0.f;

    for (int k = 0; k < 256; k += 4) {
        float4 xr[8];
        #pragma unroll
        for (int r = 0; r < 8; r++)
            xr[r] = *(const float4*)(Xsm + (warp * 8 + r) * 256 + k);
        #pragma unroll
        for (int kk = 0; kk < 4; kk++) {
            const float4 wv = ((const float4*)(Ws + (k + kk) * EMB))[lane];
            #pragma unroll
            for (int r = 0; r < 8; r++) {
                const float xk = (kk == 0) ? xr[r].x : (kk == 1) ? xr[r].y
                               : (kk == 2) ? xr[r].z : xr[r].w;
                acc[r][0] += xk * wv.x; acc[r][1] += xk * wv.y;
                acc[r][2] += xk * wv.z; acc[r][3] += xk * wv.w;
            }
        }
    }

    const float4 bmv  = ((const float4*)bm)[lane];
    const float4 gmv  = ((const float4*)gm)[lane];
    const float4 blnv = ((const float4*)bmln)[lane];

    #pragma unroll
    for (int r = 0; r < 8; r++) {
        float y0 = fmaxf(acc[r][0] + bmv.x, 0.f);
        float y1 = fmaxf(acc[r][1] + bmv.y, 0.f);
        float y2 = fmaxf(acc[r][2] + bmv.z, 0.f);
        float y3 = fmaxf(acc[r][3] + bmv.w, 0.f);
        float s  = y0 + y1 + y2 + y3;
        float ss = y0*y0 + y1*y1 + y2*y2 + y3*y3;
        #pragma unroll
        for (int o = 16; o; o >>= 1) {
            s  += __shfl_xor_sync(0xffffffffu, s,  o);
            ss += __shfl_xor_sync(0xffffffffu, ss, o);
        }
        const float mu   = s * (1.f / EMB);
        const float rstd = rsqrtf(ss * (1.f / EMB) - mu * mu + 1e-5f);
        const int row = row0 + warp * 8 + r;
        if (row < N) {
            const float4 hv = ((const float4*)(Xsm + (warp * 8 + r) * 256))[lane];
            float4 o;
            o.x = hv.x + ((y0 - mu) * rstd * gmv.x + blnv.x);
            o.y = hv.y + ((y1 - mu) * rstd * gmv.y + blnv.y);
            o.z = hv.z + ((y2 - mu) * rstd * gmv.z + blnv.z);
            o.w = hv.w + ((y3 - mu) * rstd * gmv.w + blnv.w);
            ((float4*)(dst + (size_t)row * EMB))[lane] = o;
        }
    }
}

// =====================================================================
// host
// =====================================================================
extern "C" void kernel_launch(void* const* d_in, const int* in_sizes, int n_in,
                              void* d_out, int out_size)
{
    const float* variable_emb   = (const float*)d_in[0];
    const float* edge_emb       = (const float*)d_in[1];
    const float* constraint_emb = (const float*)d_in[2];
    const int*   e_u            = (const int*)  d_in[3];
    const int*   e_v            = (const int*)  d_in[4];
    const float* W_left   = (const float*)d_in[5];
    const float* b_left   = (const float*)d_in[6];
    const float* W_edge   = (const float*)d_in[7];
    const float* W_right  = (const float*)d_in[8];
    const float* W_join   = (const float*)d_in[9];
    const float* b_join   = (const float*)d_in[10];
    const float* W_merge  = (const float*)d_in[11];
    const float* b_merge  = (const float*)d_in[12];
    const float* g_var    = (const float*)d_in[13];
    const float* b_var    = (const float*)d_in[14];
    const float* g_edge   = (const float*)d_in[15];
    const float* b_edge   = (const float*)d_in[16];
    const float* g_con    = (const float*)d_in[17];
    const float* b_con    = (const float*)d_in[18];
    const float* g_join_ln  = (const float*)d_in[19];
    const float* b_join_ln  = (const float*)d_in[20];
    const float* g_joint    = (const float*)d_in[21];
    const float* b_joint    = (const float*)d_in[22];
    const float* g_merge    = (const float*)d_in[23];
    const float* b_merge_ln = (const float*)d_in[24];

    float* out_var = (float*)d_out;
    float* out_con = (float*)d_out + (size_t)NUv * EMB;

    float *vt, *et, *ct, *agg;
    cudaGetSymbolAddress((void**)&vt,  g_vt);
    cudaGetSymbolAddress((void**)&et,  g_et);
    cudaGetSymbolAddress((void**)&ct,  g_ct);
    cudaGetSymbolAddress((void**)&agg, g_agg);

    const int SM_MMA   = (64 * WP_STRIDE + 64 * XS_STRIDE) * 4;        // 101,376 B
    const int SM_MERGE = (2 * EMB * EMB + 64 * 256) * sizeof(float);   // 192 KB

    cudaFuncSetAttribute(ln_gemm_tf32,   cudaFuncAttributeMaxDynamicSharedMemorySize, SM_MMA);
    cudaFuncSetAttribute(edge_join_tf32, cudaFuncAttributeMaxDynamicSharedMemorySize, SM_MMA);
    cudaFuncSetAttribute(merge_kernel,   cudaFuncAttributeMaxDynamicSharedMemorySize, SM_MERGE);

    const dim3 blk(256);
    const int gb_u = (NUv + 63) / 64;
    const int gb_v = (NVv + 63) / 64;
    const int gb_e = (NEv + 63) / 64;

    // shared pre-transforms (vt and et identical in both passes)
    ln_gemm_tf32<<<gb_u, blk, SM_MMA>>>(variable_emb, W_left, b_left, g_var, b_var, vt, NUv);
    ln_gemm_tf32<<<gb_e, blk, SM_MMA>>>(edge_emb, W_edge, nullptr, g_edge, b_edge, et, NEv);
    ln_gemm_tf32<<<gb_v, blk, SM_MMA>>>(constraint_emb, W_right, nullptr, g_con, b_con, ct, NVv);

    // ---------------- pass 1: var -> con ----------------
    cudaMemsetAsync(agg, 0, (size_t)NVv * EMB * sizeof(float), 0);
    edge_join_tf32<<<gb_e, blk, SM_MMA>>>(vt, et, ct, e_u, e_v, W_join, b_join,
                                          g_join_ln, b_join_ln, g_joint, b_joint,
                                          agg, /*seg_by_ev=*/1, NEv);
    merge_kernel<<<gb_v, blk, SM_MERGE>>>(ct, agg, W_merge, b_merge, g_merge, b_merge_ln,
                                          out_con, NVv);

    // ---------------- pass 2: con -> var ----------------
    ln_gemm_tf32<<<gb_v, blk, SM_MMA>>>(out_con, W_right, nullptr, g_con, b_con, ct, NVv);
    cudaMemsetAsync(agg, 0, (size_t)NUv * EMB * sizeof(float), 0);
    edge_join_tf32<<<gb_e, blk, SM_MMA>>>(vt, et, ct, e_u, e_v, W_join, b_join,
                                          g_join_ln, b_join_ln, g_joint, b_joint,
                                          agg, /*seg_by_ev=*/0, NEv);
    merge_kernel<<<gb_u, blk, SM_MERGE>>>(vt, agg, W_merge, b_merge, g_merge, b_merge_ln,
                                          out_var, NUv);
}

// round 7
// speedup vs baseline: 1.9499x; 1.2105x over previous
#include <cuda_runtime.h>
#include <cuda_bf16.h>
#include <math.h>
#include <stdint.h>

#define EMB   128
#define NUv   100000
#define NVv   50000
#define NEv   500000

#define WP_STRIDE 264   // words per (kt,tig) W pair-row (paired b0,b1) -> LDS.64 B-frags
#define XS_STRIDE 132   // words per X row -> conflict-free A-frag LDS

// ---------------- scratch (device globals: allocation-guard-safe) ----------
__device__ float g_vt[(size_t)NUv * EMB];
__device__ float g_et[(size_t)NEv * EMB];
__device__ float g_ct[(size_t)NVv * EMB];
__device__ float g_agg[(size_t)NUv * EMB];

// ---------------- tf32 helpers ----------------
__device__ __forceinline__ uint32_t f2tf(float x) {
    uint32_t r;
    asm("cvt.rna.tf32.f32 %0, %1;" : "=r"(r) : "f"(x));
    return r;
}

__device__ __forceinline__ void mma8(float& c0, float& c1, float& c2, float& c3,
                                     uint32_t a0, uint32_t a1, uint32_t a2, uint32_t a3,
                                     uint32_t b0, uint32_t b1)
{
    asm volatile(
        "mma.sync.aligned.m16n8k8.row.col.f32.tf32.tf32.f32 "
        "{%0,%1,%2,%3}, {%4,%5,%6,%7}, {%8,%9}, {%0,%1,%2,%3};"
        : "+f"(c0), "+f"(c1), "+f"(c2), "+f"(c3)
        : "r"(a0), "r"(a1), "r"(a2), "r"(a3), "r"(b0), "r"(b1));
}

__device__ __forceinline__ void red_v4(float* p, float v0, float v1, float v2, float v3)
{
    asm volatile("red.global.add.v4.f32 [%0], {%1,%2,%3,%4};"
                 :: "l"(p), "f"(v0), "f"(v1), "f"(v2), "f"(v3) : "memory");
}

// Vectorized staging of W[128][128] ([k][n]) into paired-tf32 smem:
//   Wp[(kt*4+tig)*WP_STRIDE + 2*n + half], k = kt*8 + half*4 + tig
// Each thread: 2x LDG.128 (rows k0, k0+4, 4 cols) -> interleave -> 2x STS.128.
__device__ __forceinline__ void stage_W_tf32(const float* __restrict__ W,
                                             uint32_t* __restrict__ Wp,
                                             int tid, int nthreads)
{
    #pragma unroll 2
    for (int i = tid; i < 64 * 32; i += nthreads) {
        const int pr = i >> 5;         // pair-row 0..63 = kt*4 + tig
        const int c4 = i & 31;         // float4 column chunk, n = 4*c4
        const int kt = pr >> 2, tig = pr & 3;
        const int k0 = kt * 8 + tig;
        const float4 w0 = ((const float4*)(W + (size_t)k0 * EMB))[c4];
        const float4 w1 = ((const float4*)(W + (size_t)(k0 + 4) * EMB))[c4];
        uint32_t* dst = Wp + pr * WP_STRIDE + 8 * c4;
        uint4 lo, hi;
        lo.x = f2tf(w0.x); lo.y = f2tf(w1.x); lo.z = f2tf(w0.y); lo.w = f2tf(w1.y);
        hi.x = f2tf(w0.z); hi.y = f2tf(w1.z); hi.z = f2tf(w0.w); hi.w = f2tf(w1.w);
        ((uint4*)dst)[0] = lo;
        ((uint4*)dst)[1] = hi;
    }
}

// Warp mainloop over HALF the N dim: rows [r0, r0+16), cols [ch*64, ch*64+64)
__device__ __forceinline__ void mma_mainloop_half(const uint32_t* __restrict__ Xs,
                                                  const uint32_t* __restrict__ Wp,
                                                  int r0, int gq, int tig, int ch,
                                                  float acc[8][4])
{
    #pragma unroll
    for (int kt = 0; kt < 16; ++kt) {
        const uint32_t* xl = Xs + (r0 + gq) * XS_STRIDE + kt * 8;
        const uint32_t* xh = Xs + (r0 + gq + 8) * XS_STRIDE + kt * 8;
        const uint32_t a0 = xl[tig];
        const uint32_t a1 = xh[tig];
        const uint32_t a2 = xl[tig + 4];
        const uint32_t a3 = xh[tig + 4];
        const uint32_t* wrow = Wp + (kt * 4 + tig) * WP_STRIDE + 2 * (ch * 64);
        uint2 b[8];
        #pragma unroll
        for (int nt = 0; nt < 8; ++nt)
            b[nt] = *(const uint2*)(wrow + 2 * (nt * 8 + gq));
        #pragma unroll
        for (int nt = 0; nt < 8; ++nt)
            mma8(acc[nt][0], acc[nt][1], acc[nt][2], acc[nt][3],
                 a0, a1, a2, a3, b[nt].x, b[nt].y);
    }
}

// =====================================================================
// Kernel 1 (tf32): Y[row] = LN(X[row]; g,b) @ W (+bias)
// block = 256 threads (8 warps), tile 64 rows.
// =====================================================================
__global__ __launch_bounds__(256, 2)
void ln_gemm_tf32(const float* __restrict__ X, const float* __restrict__ W,
                  const float* __restrict__ bias,
                  const float* __restrict__ g, const float* __restrict__ b,
                  float* __restrict__ Y, int N)
{
    extern __shared__ uint32_t smu[];
    uint32_t* Wp = smu;                       // 64*264 words
    uint32_t* Xs = smu + 64 * WP_STRIDE;      // 64*132 words
    float*    Xf = (float*)Xs;

    const int tid  = threadIdx.x;
    const int lane = tid & 31;
    const int warp = tid >> 5;
    const int gq   = lane >> 2;
    const int tig  = lane & 3;
    const int r0   = (warp >> 1) * 16;
    const int ch   = warp & 1;

    stage_W_tf32(W, Wp, tid, 256);

    const int row0 = blockIdx.x * 64;

    const float4 gv = ((const float4*)g)[lane];
    const float4 bv = ((const float4*)b)[lane];

    // stage + LN + tf32 convert: warp w -> rows w*8..w*8+7
    #pragma unroll
    for (int r = 0; r < 8; ++r) {
        const int lr  = warp * 8 + r;
        const int row = row0 + lr;
        float4 xv = make_float4(0.f, 0.f, 0.f, 0.f);
        if (row < N) xv = ((const float4*)(X + (size_t)row * EMB))[lane];
        float s  = xv.x + xv.y + xv.z + xv.w;
        float ss = xv.x * xv.x + xv.y * xv.y + xv.z * xv.z + xv.w * xv.w;
        #pragma unroll
        for (int o = 16; o; o >>= 1) {
            s  += __shfl_xor_sync(0xffffffffu, s,  o);
            ss += __shfl_xor_sync(0xffffffffu, ss, o);
        }
        const float mu   = s * (1.f / EMB);
        const float rstd = rsqrtf(ss * (1.f / EMB) - mu * mu + 1e-5f);
        uint4 q;
        q.x = f2tf((xv.x - mu) * rstd * gv.x + bv.x);
        q.y = f2tf((xv.y - mu) * rstd * gv.y + bv.y);
        q.z = f2tf((xv.z - mu) * rstd * gv.z + bv.z);
        q.w = f2tf((xv.w - mu) * rstd * gv.w + bv.w);
        *(uint4*)(Xs + lr * XS_STRIDE + lane * 4) = q;
    }
    __syncthreads();

    float acc[8][4];
    #pragma unroll
    for (int i = 0; i < 8; ++i)
        #pragma unroll
        for (int j = 0; j < 4; ++j) acc[i][j] = 0.f;

    mma_mainloop_half(Xs, Wp, r0, gq, tig, ch, acc);

    // repack through Xs for coalesced stores
    __syncthreads();
    #pragma unroll
    for (int nt = 0; nt < 8; ++nt) {
        const int col = ch * 64 + nt * 8 + 2 * tig;
        float* rl = Xf + (r0 + gq)     * XS_STRIDE + col;
        float* rh = Xf + (r0 + gq + 8) * XS_STRIDE + col;
        rl[0] = acc[nt][0]; rl[1] = acc[nt][1];
        rh[0] = acc[nt][2]; rh[1] = acc[nt][3];
    }
    __syncthreads();

    float4 bb = make_float4(0.f, 0.f, 0.f, 0.f);
    if (bias) bb = ((const float4*)bias)[lane];
    #pragma unroll
    for (int r = 0; r < 8; ++r) {
        const int lr  = warp * 8 + r;
        const int row = row0 + lr;
        if (row < N) {
            float4 o = ((const float4*)(Xf + lr * XS_STRIDE))[lane];
            o.x += bb.x; o.y += bb.y; o.z += bb.z; o.w += bb.w;
            ((float4*)(Y + (size_t)row * EMB))[lane] = o;
        }
    }
}

// =====================================================================
// Kernel 2 (tf32): fused edge join + LN + GEMM + LN + vec4 red scatter
// block = 256 threads (8 warps), 64 edges.
// =====================================================================
__global__ __launch_bounds__(256, 2)
void edge_join_tf32(const float* __restrict__ vt, const float* __restrict__ et,
                    const float* __restrict__ ct,
                    const int* __restrict__ e_u, const int* __restrict__ e_v,
                    const float* __restrict__ Wj, const float* __restrict__ bj,
                    const float* __restrict__ g1, const float* __restrict__ b1,
                    const float* __restrict__ g2, const float* __restrict__ b2,
                    float* __restrict__ agg, int seg_by_ev, int NE)
{
    extern __shared__ uint32_t smu[];
    uint32_t* Wp = smu;
    uint32_t* Xs = smu + 64 * WP_STRIDE;
    __shared__ int   segs[64];
    __shared__ float sP[64][2], ssP[64][2];

    const int tid  = threadIdx.x;
    const int lane = tid & 31;
    const int warp = tid >> 5;
    const int gq   = lane >> 2;
    const int tig  = lane & 3;
    const int r0   = (warp >> 1) * 16;
    const int ch   = warp & 1;

    stage_W_tf32(Wj, Wp, tid, 256);

    const int e0 = blockIdx.x * 64;
    const float4 g1v = ((const float4*)g1)[lane];
    const float4 b1v = ((const float4*)b1)[lane];

    // batch indices first (MLP), then gather + relu + LN + tf32 convert
    int iu[8], iv[8];
    #pragma unroll
    for (int r = 0; r < 8; ++r) {
        const int e = e0 + warp * 8 + r;
        iu[r] = (e < NE) ? __ldg(e_u + e) : -1;
        iv[r] = (e < NE) ? __ldg(e_v + e) : -1;
    }
    if (lane == 0) {
        #pragma unroll
        for (int r = 0; r < 8; ++r)
            segs[warp * 8 + r] = (iu[r] < 0) ? -1 : (seg_by_ev ? iv[r] : iu[r]);
    }

    #pragma unroll
    for (int r = 0; r < 8; ++r) {
        const int lr = warp * 8 + r;
        const int e  = e0 + lr;
        float4 xv = make_float4(0.f, 0.f, 0.f, 0.f);
        if (iu[r] >= 0) {
            const float4 a = ((const float4*)(vt + (size_t)iu[r] * EMB))[lane];
            const float4 m = ((const float4*)(et + (size_t)e     * EMB))[lane];
            const float4 c = ((const float4*)(ct + (size_t)iv[r] * EMB))[lane];
            xv.x = fmaxf(a.x + m.x + c.x, 0.f);
            xv.y = fmaxf(a.y + m.y + c.y, 0.f);
            xv.z = fmaxf(a.z + m.z + c.z, 0.f);
            xv.w = fmaxf(a.w + m.w + c.w, 0.f);
        }
        float s  = xv.x + xv.y + xv.z + xv.w;
        float ss = xv.x * xv.x + xv.y * xv.y + xv.z * xv.z + xv.w * xv.w;
        #pragma unroll
        for (int o = 16; o; o >>= 1) {
            s  += __shfl_xor_sync(0xffffffffu, s,  o);
            ss += __shfl_xor_sync(0xffffffffu, ss, o);
        }
        const float mu   = s * (1.f / EMB);
        const float rstd = rsqrtf(ss * (1.f / EMB) - mu * mu + 1e-5f);
        uint4 q;
        q.x = f2tf((xv.x - mu) * rstd * g1v.x + b1v.x);
        q.y = f2tf((xv.y - mu) * rstd * g1v.y + b1v.y);
        q.z = f2tf((xv.z - mu) * rstd * g1v.z + b1v.z);
        q.w = f2tf((xv.w - mu) * rstd * g1v.w + b1v.w);
        *(uint4*)(Xs + lr * XS_STRIDE + lane * 4) = q;
    }
    __syncthreads();

    float acc[8][4];
    #pragma unroll
    for (int i = 0; i < 8; ++i)
        #pragma unroll
        for (int j = 0; j < 4; ++j) acc[i][j] = 0.f;

    mma_mainloop_half(Xs, Wp, r0, gq, tig, ch, acc);

    // ---- epilogue: +bias, cross-warp LN stats ----
    float s_lo = 0.f, ss_lo = 0.f, s_hi = 0.f, ss_hi = 0.f;
    #pragma unroll
    for (int nt = 0; nt < 8; ++nt) {
        const int col = ch * 64 + nt * 8 + 2 * tig;
        const float2 bjv = *(const float2*)(bj + col);
        acc[nt][0] += bjv.x; acc[nt][1] += bjv.y;
        acc[nt][2] += bjv.x; acc[nt][3] += bjv.y;
        s_lo  += acc[nt][0] + acc[nt][1];
        ss_lo += acc[nt][0] * acc[nt][0] + acc[nt][1] * acc[nt][1];
        s_hi  += acc[nt][2] + acc[nt][3];
        ss_hi += acc[nt][2] * acc[nt][2] + acc[nt][3] * acc[nt][3];
    }
    #pragma unroll
    for (int o = 1; o < 4; o <<= 1) {
        s_lo  += __shfl_xor_sync(0xffffffffu, s_lo,  o);
        ss_lo += __shfl_xor_sync(0xffffffffu, ss_lo, o);
        s_hi  += __shfl_xor_sync(0xffffffffu, s_hi,  o);
        ss_hi += __shfl_xor_sync(0xffffffffu, ss_hi, o);
    }
    if (tig == 0) {
        sP [r0 + gq][ch]     = s_lo;  ssP[r0 + gq][ch]     = ss_lo;
        sP [r0 + gq + 8][ch] = s_hi;  ssP[r0 + gq + 8][ch] = ss_hi;
    }
    __syncthreads();

    const float st_lo  = sP [r0 + gq][0]     + sP [r0 + gq][1];
    const float sst_lo = ssP[r0 + gq][0]     + ssP[r0 + gq][1];
    const float st_hi  = sP [r0 + gq + 8][0] + sP [r0 + gq + 8][1];
    const float sst_hi = ssP[r0 + gq + 8][0] + ssP[r0 + gq + 8][1];
    const float mu_lo   = st_lo * (1.f / EMB);
    const float rstd_lo = rsqrtf(sst_lo * (1.f / EMB) - mu_lo * mu_lo + 1e-5f);
    const float mu_hi   = st_hi * (1.f / EMB);
    const float rstd_hi = rsqrtf(sst_hi * (1.f / EMB) - mu_hi * mu_hi + 1e-5f);

    const int  seg_lo = segs[r0 + gq];
    const int  seg_hi = segs[r0 + gq + 8];
    const bool odd    = (tig & 1);
    const float mu    = odd ? mu_hi   : mu_lo;
    const float rstd  = odd ? rstd_hi : rstd_lo;
    const int   seg   = odd ? seg_hi  : seg_lo;
    float* base = agg + (size_t)(seg < 0 ? 0 : seg) * EMB;

    // repack (2col x 2row) frags -> 4 contiguous cols of one row, red.v4
    #pragma unroll
    for (int nt = 0; nt < 8; ++nt) {
        const float l0 = acc[nt][0], l1 = acc[nt][1];
        const float h0 = acc[nt][2], h1 = acc[nt][3];
        const float p0 = __shfl_xor_sync(0xffffffffu, odd ? l0 : h0, 1);
        const float p1 = __shfl_xor_sync(0xffffffffu, odd ? l1 : h1, 1);
        float v0, v1, v2, v3;
        if (!odd) { v0 = l0; v1 = l1; v2 = p0; v3 = p1; }
        else      { v0 = p0; v1 = p1; v2 = h0; v3 = h1; }
        const int col = ch * 64 + nt * 8 + (tig >> 1) * 4;
        const float4 gg  = *(const float4*)(g2 + col);
        const float4 b2v = *(const float4*)(b2 + col);
        v0 = (v0 - mu) * rstd * gg.x + b2v.x;
        v1 = (v1 - mu) * rstd * gg.y + b2v.y;
        v2 = (v2 - mu) * rstd * gg.z + b2v.z;
        v3 = (v3 - mu) * rstd * gg.w + b2v.w;
        if (seg >= 0) red_v4(base + col, v0, v1, v2, v3);
    }
}

// =====================================================================
// Kernel 3: merge (fp32 FFMA):
//   out = LN(relu(concat([h, agg]) @ W_merge + b_merge)); dst = h + out
// =====================================================================
__global__ __launch_bounds__(256, 1)
void merge_kernel(const float* __restrict__ h, const float* __restrict__ agg,
                  const float* __restrict__ Wm, const float* __restrict__ bm,
                  const float* __restrict__ gm, const float* __restrict__ bmln,
                  float* __restrict__ dst, int N)
{
    extern __shared__ float sm[];
    float* Ws  = sm;                   // 256*128
    float* Xsm = sm + 2 * EMB * EMB;   // 64*256

    const int tid  = threadIdx.x;
    const int lane = tid & 31;
    const int warp = tid >> 5;

    {
        const float4* W4  = (const float4*)Wm;
        float4*       Ws4 = (float4*)Ws;
        #pragma unroll
        for (int i = tid; i < 2 * EMB * EMB / 4; i += 256) Ws4[i] = W4[i];
    }

    const int row0 = blockIdx.x * 64;
    #pragma unroll
    for (int r = 0; r < 8; r++) {
        const int row = row0 + warp * 8 + r;
        float4 hv = make_float4(0.f, 0.f, 0.f, 0.f);
        float4 av = make_float4(0.f, 0.f, 0.f, 0.f);
        if (row < N) {
            hv = ((const float4*)(h   + (size_t)row * EMB))[lane];
            av = ((const float4*)(agg + (size_t)row * EMB))[lane];
        }
        ((float4*)(Xsm + (warp * 8 + r) * 256))[lane]       = hv;
        ((float4*)(Xsm + (warp * 8 + r) * 256 + EMB))[lane] = av;
    }
    __syncthreads();

    float acc[8][4];
    #pragma unroll
    for (int r = 0; r < 8; r++)
        #pragma unroll
        for (int i = 0; i < 4; i++) acc[r][i] = 0.f;

    for (int k = 0; k < 256; k += 4) {
        float4 xr[8];
        #pragma unroll
        for (int r = 0; r < 8; r++)
            xr[r] = *(const float4*)(Xsm + (warp * 8 + r) * 256 + k);
        #pragma unroll
        for (int kk = 0; kk < 4; kk++) {
            const float4 wv = ((const float4*)(Ws + (k + kk) * EMB))[lane];
            #pragma unroll
            for (int r = 0; r < 8; r++) {
                const float xk = (kk == 0) ? xr[r].x : (kk == 1) ? xr[r].y
                               : (kk == 2) ? xr[r].z : xr[r].w;
                acc[r][0] += xk * wv.x; acc[r][1] += xk * wv.y;
                acc[r][2] += xk * wv.z; acc[r][3] += xk * wv.w;
            }
        }
    }

    const float4 bmv  = ((const float4*)bm)[lane];
    const float4 gmv  = ((const float4*)gm)[lane];
    const float4 blnv = ((const float4*)bmln)[lane];

    #pragma unroll
    for (int r = 0; r < 8; r++) {
        float y0 = fmaxf(acc[r][0] + bmv.x, 0.f);
        float y1 = fmaxf(acc[r][1] + bmv.y, 0.f);
        float y2 = fmaxf(acc[r][2] + bmv.z, 0.f);
        float y3 = fmaxf(acc[r][3] + bmv.w, 0.f);
        float s  = y0 + y1 + y2 + y3;
        float ss = y0*y0 + y1*y1 + y2*y2 + y3*y3;
        #pragma unroll
        for (int o = 16; o; o >>= 1) {
            s  += __shfl_xor_sync(0xffffffffu, s,  o);
            ss += __shfl_xor_sync(0xffffffffu, ss, o);
        }
        const float mu   = s * (1.f / EMB);
        const float rstd = rsqrtf(ss * (1.f / EMB) - mu * mu + 1e-5f);
        const int row = row0 + warp * 8 + r;
        if (row < N) {
            const float4 hv = ((const float4*)(Xsm + (warp * 8 + r) * 256))[lane];
            float4 o;
            o.x = hv.x + ((y0 - mu) * rstd * gmv.x + blnv.x);
            o.y = hv.y + ((y1 - mu) * rstd * gmv.y + blnv.y);
            o.z = hv.z + ((y2 - mu) * rstd * gmv.z + blnv.z);
            o.w = hv.w + ((y3 - mu) * rstd * gmv.w + blnv.w);
            ((float4*)(dst + (size_t)row * EMB))[lane] = o;
        }
    }
}

// =====================================================================
// host
// =====================================================================
extern "C" void kernel_launch(void* const* d_in, const int* in_sizes, int n_in,
                              void* d_out, int out_size)
{
    const float* variable_emb   = (const float*)d_in[0];
    const float* edge_emb       = (const float*)d_in[1];
    const float* constraint_emb = (const float*)d_in[2];
    const int*   e_u            = (const int*)  d_in[3];
    const int*   e_v            = (const int*)  d_in[4];
    const float* W_left   = (const float*)d_in[5];
    const float* b_left   = (const float*)d_in[6];
    const float* W_edge   = (const float*)d_in[7];
    const float* W_right  = (const float*)d_in[8];
    const float* W_join   = (const float*)d_in[9];
    const float* b_join   = (const float*)d_in[10];
    const float* W_merge  = (const float*)d_in[11];
    const float* b_merge  = (const float*)d_in[12];
    const float* g_var    = (const float*)d_in[13];
    const float* b_var    = (const float*)d_in[14];
    const float* g_edge   = (const float*)d_in[15];
    const float* b_edge   = (const float*)d_in[16];
    const float* g_con    = (const float*)d_in[17];
    const float* b_con    = (const float*)d_in[18];
    const float* g_join_ln  = (const float*)d_in[19];
    const float* b_join_ln  = (const float*)d_in[20];
    const float* g_joint    = (const float*)d_in[21];
    const float* b_joint    = (const float*)d_in[22];
    const float* g_merge    = (const float*)d_in[23];
    const float* b_merge_ln = (const float*)d_in[24];

    float* out_var = (float*)d_out;
    float* out_con = (float*)d_out + (size_t)NUv * EMB;

    float *vt, *et, *ct, *agg;
    cudaGetSymbolAddress((void**)&vt,  g_vt);
    cudaGetSymbolAddress((void**)&et,  g_et);
    cudaGetSymbolAddress((void**)&ct,  g_ct);
    cudaGetSymbolAddress((void**)&agg, g_agg);

    const int SM_MMA   = (64 * WP_STRIDE + 64 * XS_STRIDE) * 4;        // 101,376 B
    const int SM_MERGE = (2 * EMB * EMB + 64 * 256) * sizeof(float);   // 192 KB

    cudaFuncSetAttribute(ln_gemm_tf32,   cudaFuncAttributeMaxDynamicSharedMemorySize, SM_MMA);
    cudaFuncSetAttribute(edge_join_tf32, cudaFuncAttributeMaxDynamicSharedMemorySize, SM_MMA);
    cudaFuncSetAttribute(merge_kernel,   cudaFuncAttributeMaxDynamicSharedMemorySize, SM_MERGE);

    const dim3 blk(256);
    const int gb_u = (NUv + 63) / 64;
    const int gb_v = (NVv + 63) / 64;
    const int gb_e = (NEv + 63) / 64;

    // shared pre-transforms (vt and et identical in both passes)
    ln_gemm_tf32<<<gb_u, blk, SM_MMA>>>(variable_emb, W_left, b_left, g_var, b_var, vt, NUv);
    ln_gemm_tf32<<<gb_e, blk, SM_MMA>>>(edge_emb, W_edge, nullptr, g_edge, b_edge, et, NEv);
    ln_gemm_tf32<<<gb_v, blk, SM_MMA>>>(constraint_emb, W_right, nullptr, g_con, b_con, ct, NVv);

    // ---------------- pass 1: var -> con ----------------
    cudaMemsetAsync(agg, 0, (size_t)NVv * EMB * sizeof(float), 0);
    edge_join_tf32<<<gb_e, blk, SM_MMA>>>(vt, et, ct, e_u, e_v, W_join, b_join,
                                          g_join_ln, b_join_ln, g_joint, b_joint,
                                          agg, /*seg_by_ev=*/1, NEv);
    merge_kernel<<<gb_v, blk, SM_MERGE>>>(ct, agg, W_merge, b_merge, g_merge, b_merge_ln,
                                          out_con, NVv);

    // ---------------- pass 2: con -> var ----------------
    ln_gemm_tf32<<<gb_v, blk, SM_MMA>>>(out_con, W_right, nullptr, g_con, b_con, ct, NVv);
    cudaMemsetAsync(agg, 0, (size_t)NUv * EMB * sizeof(float), 0);
    edge_join_tf32<<<gb_e, blk, SM_MMA>>>(vt, et, ct, e_u, e_v, W_join, b_join,
                                          g_join_ln, b_join_ln, g_joint, b_joint,
                                          agg, /*seg_by_ev=*/0, NEv);
    merge_kernel<<<gb_u, blk, SM_MERGE>>>(vt, agg, W_merge, b_merge, g_merge, b_merge_ln,
                                          out_var, NUv);
}

// round 8
// speedup vs baseline: 2.2110x; 1.1339x over previous
#include <cuda_runtime.h>
#include <cuda_bf16.h>
#include <math.h>
#include <stdint.h>

#define EMB   128
#define NUv   100000
#define NVv   50000
#define NEv   500000

#define WP_STRIDE 264   // words per (kt,tig) W pair-row (paired b0,b1) -> LDS.64 B-frags
#define XS_STRIDE 132   // words per X row -> conflict-free A-frag LDS

#define GRID_MMA   296  // 2 blocks/SM * 148 SMs (persistent-tile)
#define GRID_MERGE 148  // 1 block/SM (192KB smem)

// ---------------- scratch (device globals: allocation-guard-safe) ----------
__device__ float g_vt[(size_t)NUv * EMB];
__device__ float g_et[(size_t)NEv * EMB];
__device__ float g_ct[(size_t)NVv * EMB];
__device__ float g_agg[(size_t)NUv * EMB];

// ---------------- tf32 helpers ----------------
__device__ __forceinline__ uint32_t f2tf(float x) {
    uint32_t r;
    asm("cvt.rna.tf32.f32 %0, %1;" : "=r"(r) : "f"(x));
    return r;
}

__device__ __forceinline__ void mma8(float& c0, float& c1, float& c2, float& c3,
                                     uint32_t a0, uint32_t a1, uint32_t a2, uint32_t a3,
                                     uint32_t b0, uint32_t b1)
{
    asm volatile(
        "mma.sync.aligned.m16n8k8.row.col.f32.tf32.tf32.f32 "
        "{%0,%1,%2,%3}, {%4,%5,%6,%7}, {%8,%9}, {%0,%1,%2,%3};"
        : "+f"(c0), "+f"(c1), "+f"(c2), "+f"(c3)
        : "r"(a0), "r"(a1), "r"(a2), "r"(a3), "r"(b0), "r"(b1));
}

__device__ __forceinline__ void red_v4(float* p, float v0, float v1, float v2, float v3)
{
    asm volatile("red.global.add.v4.f32 [%0], {%1,%2,%3,%4};"
                 :: "l"(p), "f"(v0), "f"(v1), "f"(v2), "f"(v3) : "memory");
}

// Vectorized staging of W[128][128] ([k][n]) into paired-tf32 smem:
//   Wp[(kt*4+tig)*WP_STRIDE + 2*n + half], k = kt*8 + half*4 + tig
__device__ __forceinline__ void stage_W_tf32(const float* __restrict__ W,
                                             uint32_t* __restrict__ Wp,
                                             int tid, int nthreads)
{
    #pragma unroll 2
    for (int i = tid; i < 64 * 32; i += nthreads) {
        const int pr = i >> 5;
        const int c4 = i & 31;
        const int kt = pr >> 2, tig = pr & 3;
        const int k0 = kt * 8 + tig;
        const float4 w0 = ((const float4*)(W + (size_t)k0 * EMB))[c4];
        const float4 w1 = ((const float4*)(W + (size_t)(k0 + 4) * EMB))[c4];
        uint32_t* dst = Wp + pr * WP_STRIDE + 8 * c4;
        uint4 lo, hi;
        lo.x = f2tf(w0.x); lo.y = f2tf(w1.x); lo.z = f2tf(w0.y); lo.w = f2tf(w1.y);
        hi.x = f2tf(w0.z); hi.y = f2tf(w1.z); hi.z = f2tf(w0.w); hi.w = f2tf(w1.w);
        ((uint4*)dst)[0] = lo;
        ((uint4*)dst)[1] = hi;
    }
}

// Warp mainloop over HALF the N dim: rows [r0, r0+16), cols [ch*64, ch*64+64)
__device__ __forceinline__ void mma_mainloop_half(const uint32_t* __restrict__ Xs,
                                                  const uint32_t* __restrict__ Wp,
                                                  int r0, int gq, int tig, int ch,
                                                  float acc[8][4])
{
    #pragma unroll
    for (int kt = 0; kt < 16; ++kt) {
        const uint32_t* xl = Xs + (r0 + gq) * XS_STRIDE + kt * 8;
        const uint32_t* xh = Xs + (r0 + gq + 8) * XS_STRIDE + kt * 8;
        const uint32_t a0 = xl[tig];
        const uint32_t a1 = xh[tig];
        const uint32_t a2 = xl[tig + 4];
        const uint32_t a3 = xh[tig + 4];
        const uint32_t* wrow = Wp + (kt * 4 + tig) * WP_STRIDE + 2 * (ch * 64);
        uint2 b[8];
        #pragma unroll
        for (int nt = 0; nt < 8; ++nt)
            b[nt] = *(const uint2*)(wrow + 2 * (nt * 8 + gq));
        #pragma unroll
        for (int nt = 0; nt < 8; ++nt)
            mma8(acc[nt][0], acc[nt][1], acc[nt][2], acc[nt][3],
                 a0, a1, a2, a3, b[nt].x, b[nt].y);
    }
}

// =====================================================================
// Kernel 1 (tf32, persistent): Y[row] = LN(X[row]; g,b) @ W (+bias)
// =====================================================================
__global__ __launch_bounds__(256, 2)
void ln_gemm_tf32(const float* __restrict__ X, const float* __restrict__ W,
                  const float* __restrict__ bias,
                  const float* __restrict__ g, const float* __restrict__ b,
                  float* __restrict__ Y, int N)
{
    extern __shared__ uint32_t smu[];
    uint32_t* Wp = smu;
    uint32_t* Xs = smu + 64 * WP_STRIDE;
    float*    Xf = (float*)Xs;

    const int tid  = threadIdx.x;
    const int lane = tid & 31;
    const int warp = tid >> 5;
    const int gq   = lane >> 2;
    const int tig  = lane & 3;
    const int r0   = (warp >> 1) * 16;
    const int ch   = warp & 1;

    stage_W_tf32(W, Wp, tid, 256);

    const float4 gv = ((const float4*)g)[lane];
    const float4 bv = ((const float4*)b)[lane];
    float4 bb = make_float4(0.f, 0.f, 0.f, 0.f);
    if (bias) bb = ((const float4*)bias)[lane];

    const int nTiles = (N + 63) >> 6;
    for (int tile = blockIdx.x; tile < nTiles; tile += gridDim.x) {
        const int row0 = tile * 64;
        __syncthreads();   // protect Xs from previous tile's readers

        #pragma unroll
        for (int r = 0; r < 8; ++r) {
            const int lr  = warp * 8 + r;
            const int row = row0 + lr;
            float4 xv = make_float4(0.f, 0.f, 0.f, 0.f);
            if (row < N) xv = ((const float4*)(X + (size_t)row * EMB))[lane];
            float s  = xv.x + xv.y + xv.z + xv.w;
            float ss = xv.x * xv.x + xv.y * xv.y + xv.z * xv.z + xv.w * xv.w;
            #pragma unroll
            for (int o = 16; o; o >>= 1) {
                s  += __shfl_xor_sync(0xffffffffu, s,  o);
                ss += __shfl_xor_sync(0xffffffffu, ss, o);
            }
            const float mu   = s * (1.f / EMB);
            const float rstd = rsqrtf(ss * (1.f / EMB) - mu * mu + 1e-5f);
            uint4 q;
            q.x = f2tf((xv.x - mu) * rstd * gv.x + bv.x);
            q.y = f2tf((xv.y - mu) * rstd * gv.y + bv.y);
            q.z = f2tf((xv.z - mu) * rstd * gv.z + bv.z);
            q.w = f2tf((xv.w - mu) * rstd * gv.w + bv.w);
            *(uint4*)(Xs + lr * XS_STRIDE + lane * 4) = q;
        }
        __syncthreads();

        float acc[8][4];
        #pragma unroll
        for (int i = 0; i < 8; ++i)
            #pragma unroll
            for (int j = 0; j < 4; ++j) acc[i][j] = 0.f;

        mma_mainloop_half(Xs, Wp, r0, gq, tig, ch, acc);

        __syncthreads();
        #pragma unroll
        for (int nt = 0; nt < 8; ++nt) {
            const int col = ch * 64 + nt * 8 + 2 * tig;
            float* rl = Xf + (r0 + gq)     * XS_STRIDE + col;
            float* rh = Xf + (r0 + gq + 8) * XS_STRIDE + col;
            rl[0] = acc[nt][0]; rl[1] = acc[nt][1];
            rh[0] = acc[nt][2]; rh[1] = acc[nt][3];
        }
        __syncthreads();

        #pragma unroll
        for (int r = 0; r < 8; ++r) {
            const int lr  = warp * 8 + r;
            const int row = row0 + lr;
            if (row < N) {
                float4 o = ((const float4*)(Xf + lr * XS_STRIDE))[lane];
                o.x += bb.x; o.y += bb.y; o.z += bb.z; o.w += bb.w;
                ((float4*)(Y + (size_t)row * EMB))[lane] = o;
            }
        }
    }
}

// =====================================================================
// Kernel 2 (tf32, persistent): fused edge join + LN + GEMM + LN + red.v4
// =====================================================================
__global__ __launch_bounds__(256, 2)
void edge_join_tf32(const float* __restrict__ vt, const float* __restrict__ et,
                    const float* __restrict__ ct,
                    const int* __restrict__ e_u, const int* __restrict__ e_v,
                    const float* __restrict__ Wj, const float* __restrict__ bj,
                    const float* __restrict__ g1, const float* __restrict__ b1,
                    const float* __restrict__ g2, const float* __restrict__ b2,
                    float* __restrict__ agg, int seg_by_ev, int NE)
{
    extern __shared__ uint32_t smu[];
    uint32_t* Wp = smu;
    uint32_t* Xs = smu + 64 * WP_STRIDE;
    __shared__ int   segs[64];
    __shared__ float sP[64][2], ssP[64][2];

    const int tid  = threadIdx.x;
    const int lane = tid & 31;
    const int warp = tid >> 5;
    const int gq   = lane >> 2;
    const int tig  = lane & 3;
    const int r0   = (warp >> 1) * 16;
    const int ch   = warp & 1;
    const bool odd = (tig & 1);

    stage_W_tf32(Wj, Wp, tid, 256);

    const float4 g1v = ((const float4*)g1)[lane];
    const float4 b1v = ((const float4*)b1)[lane];

    const int nTiles = (NE + 63) >> 6;
    for (int tile = blockIdx.x; tile < nTiles; tile += gridDim.x) {
        const int e0 = tile * 64;
        __syncthreads();   // protect Xs/segs/sP from previous tile's readers

        int iu[8], iv[8];
        #pragma unroll
        for (int r = 0; r < 8; ++r) {
            const int e = e0 + warp * 8 + r;
            iu[r] = (e < NE) ? __ldg(e_u + e) : -1;
            iv[r] = (e < NE) ? __ldg(e_v + e) : -1;
        }
        if (lane == 0) {
            #pragma unroll
            for (int r = 0; r < 8; ++r)
                segs[warp * 8 + r] = (iu[r] < 0) ? -1 : (seg_by_ev ? iv[r] : iu[r]);
        }

        #pragma unroll
        for (int r = 0; r < 8; ++r) {
            const int lr = warp * 8 + r;
            const int e  = e0 + lr;
            float4 xv = make_float4(0.f, 0.f, 0.f, 0.f);
            if (iu[r] >= 0) {
                const float4 a = ((const float4*)(vt + (size_t)iu[r] * EMB))[lane];
                const float4 m = ((const float4*)(et + (size_t)e     * EMB))[lane];
                const float4 c = ((const float4*)(ct + (size_t)iv[r] * EMB))[lane];
                xv.x = fmaxf(a.x + m.x + c.x, 0.f);
                xv.y = fmaxf(a.y + m.y + c.y, 0.f);
                xv.z = fmaxf(a.z + m.z + c.z, 0.f);
                xv.w = fmaxf(a.w + m.w + c.w, 0.f);
            }
            float s  = xv.x + xv.y + xv.z + xv.w;
            float ss = xv.x * xv.x + xv.y * xv.y + xv.z * xv.z + xv.w * xv.w;
            #pragma unroll
            for (int o = 16; o; o >>= 1) {
                s  += __shfl_xor_sync(0xffffffffu, s,  o);
                ss += __shfl_xor_sync(0xffffffffu, ss, o);
            }
            const float mu   = s * (1.f / EMB);
            const float rstd = rsqrtf(ss * (1.f / EMB) - mu * mu + 1e-5f);
            uint4 q;
            q.x = f2tf((xv.x - mu) * rstd * g1v.x + b1v.x);
            q.y = f2tf((xv.y - mu) * rstd * g1v.y + b1v.y);
            q.z = f2tf((xv.z - mu) * rstd * g1v.z + b1v.z);
            q.w = f2tf((xv.w - mu) * rstd * g1v.w + b1v.w);
            *(uint4*)(Xs + lr * XS_STRIDE + lane * 4) = q;
        }
        __syncthreads();

        float acc[8][4];
        #pragma unroll
        for (int i = 0; i < 8; ++i)
            #pragma unroll
            for (int j = 0; j < 4; ++j) acc[i][j] = 0.f;

        mma_mainloop_half(Xs, Wp, r0, gq, tig, ch, acc);

        // epilogue: +bias, cross-warp LN stats
        float s_lo = 0.f, ss_lo = 0.f, s_hi = 0.f, ss_hi = 0.f;
        #pragma unroll
        for (int nt = 0; nt < 8; ++nt) {
            const int col = ch * 64 + nt * 8 + 2 * tig;
            const float2 bjv = *(const float2*)(bj + col);
            acc[nt][0] += bjv.x; acc[nt][1] += bjv.y;
            acc[nt][2] += bjv.x; acc[nt][3] += bjv.y;
            s_lo  += acc[nt][0] + acc[nt][1];
            ss_lo += acc[nt][0] * acc[nt][0] + acc[nt][1] * acc[nt][1];
            s_hi  += acc[nt][2] + acc[nt][3];
            ss_hi += acc[nt][2] * acc[nt][2] + acc[nt][3] * acc[nt][3];
        }
        #pragma unroll
        for (int o = 1; o < 4; o <<= 1) {
            s_lo  += __shfl_xor_sync(0xffffffffu, s_lo,  o);
            ss_lo += __shfl_xor_sync(0xffffffffu, ss_lo, o);
            s_hi  += __shfl_xor_sync(0xffffffffu, s_hi,  o);
            ss_hi += __shfl_xor_sync(0xffffffffu, ss_hi, o);
        }
        if (tig == 0) {
            sP [r0 + gq][ch]     = s_lo;  ssP[r0 + gq][ch]     = ss_lo;
            sP [r0 + gq + 8][ch] = s_hi;  ssP[r0 + gq + 8][ch] = ss_hi;
        }
        __syncthreads();

        const float st_lo  = sP [r0 + gq][0]     + sP [r0 + gq][1];
        const float sst_lo = ssP[r0 + gq][0]     + ssP[r0 + gq][1];
        const float st_hi  = sP [r0 + gq + 8][0] + sP [r0 + gq + 8][1];
        const float sst_hi = ssP[r0 + gq + 8][0] + ssP[r0 + gq + 8][1];
        const float mu_lo   = st_lo * (1.f / EMB);
        const float rstd_lo = rsqrtf(sst_lo * (1.f / EMB) - mu_lo * mu_lo + 1e-5f);
        const float mu_hi   = st_hi * (1.f / EMB);
        const float rstd_hi = rsqrtf(sst_hi * (1.f / EMB) - mu_hi * mu_hi + 1e-5f);

        const int  seg_lo = segs[r0 + gq];
        const int  seg_hi = segs[r0 + gq + 8];
        const float mu    = odd ? mu_hi   : mu_lo;
        const float rstd  = odd ? rstd_hi : rstd_lo;
        const int   seg   = odd ? seg_hi  : seg_lo;
        float* base = agg + (size_t)(seg < 0 ? 0 : seg) * EMB;

        #pragma unroll
        for (int nt = 0; nt < 8; ++nt) {
            const float l0 = acc[nt][0], l1 = acc[nt][1];
            const float h0 = acc[nt][2], h1 = acc[nt][3];
            const float p0 = __shfl_xor_sync(0xffffffffu, odd ? l0 : h0, 1);
            const float p1 = __shfl_xor_sync(0xffffffffu, odd ? l1 : h1, 1);
            float v0, v1, v2, v3;
            if (!odd) { v0 = l0; v1 = l1; v2 = p0; v3 = p1; }
            else      { v0 = p0; v1 = p1; v2 = h0; v3 = h1; }
            const int col = ch * 64 + nt * 8 + (tig >> 1) * 4;
            const float4 gg  = *(const float4*)(g2 + col);
            const float4 b2v = *(const float4*)(b2 + col);
            v0 = (v0 - mu) * rstd * gg.x + b2v.x;
            v1 = (v1 - mu) * rstd * gg.y + b2v.y;
            v2 = (v2 - mu) * rstd * gg.z + b2v.z;
            v3 = (v3 - mu) * rstd * gg.w + b2v.w;
            if (seg >= 0) red_v4(base + col, v0, v1, v2, v3);
        }
    }
}

// =====================================================================
// Kernel 3 (fp32 FFMA, persistent): merge
// =====================================================================
__global__ __launch_bounds__(256, 1)
void merge_kernel(const float* __restrict__ h, const float* __restrict__ agg,
                  const float* __restrict__ Wm, const float* __restrict__ bm,
                  const float* __restrict__ gm, const float* __restrict__ bmln,
                  float* __restrict__ dst, int N)
{
    extern __shared__ float sm[];
    float* Ws  = sm;                   // 256*128
    float* Xsm = sm + 2 * EMB * EMB;   // 64*256

    const int tid  = threadIdx.x;
    const int lane = tid & 31;
    const int warp = tid >> 5;

    {
        const float4* W4  = (const float4*)Wm;
        float4*       Ws4 = (float4*)Ws;
        #pragma unroll
        for (int i = tid; i < 2 * EMB * EMB / 4; i += 256) Ws4[i] = W4[i];
    }

    const float4 bmv  = ((const float4*)bm)[lane];
    const float4 gmv  = ((const float4*)gm)[lane];
    const float4 blnv = ((const float4*)bmln)[lane];

    const int nTiles = (N + 63) >> 6;
    for (int tile = blockIdx.x; tile < nTiles; tile += gridDim.x) {
        const int row0 = tile * 64;
        __syncthreads();   // protect Xsm from previous tile's readers

        #pragma unroll
        for (int r = 0; r < 8; r++) {
            const int row = row0 + warp * 8 + r;
            float4 hv = make_float4(0.f, 0.f, 0.f, 0.f);
            float4 av = make_float4(0.f, 0.f, 0.f, 0.f);
            if (row < N) {
                hv = ((const float4*)(h   + (size_t)row * EMB))[lane];
                av = ((const float4*)(agg + (size_t)row * EMB))[lane];
            }
            ((float4*)(Xsm + (warp * 8 + r) * 256))[lane]       = hv;
            ((float4*)(Xsm + (warp * 8 + r) * 256 + EMB))[lane] = av;
        }
        __syncthreads();

        float acc[8][4];
        #pragma unroll
        for (int r = 0; r < 8; r++)
            #pragma unroll
            for (int i = 0; i < 4; i++) acc[r][i] = 0.f;

        for (int k = 0; k < 256; k += 4) {
            float4 xr[8];
            #pragma unroll
            for (int r = 0; r < 8; r++)
                xr[r] = *(const float4*)(Xsm + (warp * 8 + r) * 256 + k);
            #pragma unroll
            for (int kk = 0; kk < 4; kk++) {
                const float4 wv = ((const float4*)(Ws + (k + kk) * EMB))[lane];
                #pragma unroll
                for (int r = 0; r < 8; r++) {
                    const float xk = (kk == 0) ? xr[r].x : (kk == 1) ? xr[r].y
                                   : (kk == 2) ? xr[r].z : xr[r].w;
                    acc[r][0] += xk * wv.x; acc[r][1] += xk * wv.y;
                    acc[r][2] += xk * wv.z; acc[r][3] += xk * wv.w;
                }
            }
        }

        #pragma unroll
        for (int r = 0; r < 8; r++) {
            float y0 = fmaxf(acc[r][0] + bmv.x, 0.f);
            float y1 = fmaxf(acc[r][1] + bmv.y, 0.f);
            float y2 = fmaxf(acc[r][2] + bmv.z, 0.f);
            float y3 = fmaxf(acc[r][3] + bmv.w, 0.f);
            float s  = y0 + y1 + y2 + y3;
            float ss = y0*y0 + y1*y1 + y2*y2 + y3*y3;
            #pragma unroll
            for (int o = 16; o; o >>= 1) {
                s  += __shfl_xor_sync(0xffffffffu, s,  o);
                ss += __shfl_xor_sync(0xffffffffu, ss, o);
            }
            const float mu   = s * (1.f / EMB);
            const float rstd = rsqrtf(ss * (1.f / EMB) - mu * mu + 1e-5f);
            const int row = row0 + warp * 8 + r;
            if (row < N) {
                const float4 hv = ((const float4*)(Xsm + (warp * 8 + r) * 256))[lane];
                float4 o;
                o.x = hv.x + ((y0 - mu) * rstd * gmv.x + blnv.x);
                o.y = hv.y + ((y1 - mu) * rstd * gmv.y + blnv.y);
                o.z = hv.z + ((y2 - mu) * rstd * gmv.z + blnv.z);
                o.w = hv.w + ((y3 - mu) * rstd * gmv.w + blnv.w);
                ((float4*)(dst + (size_t)row * EMB))[lane] = o;
            }
        }
    }
}

// =====================================================================
// host
// =====================================================================
extern "C" void kernel_launch(void* const* d_in, const int* in_sizes, int n_in,
                              void* d_out, int out_size)
{
    const float* variable_emb   = (const float*)d_in[0];
    const float* edge_emb       = (const float*)d_in[1];
    const float* constraint_emb = (const float*)d_in[2];
    const int*   e_u            = (const int*)  d_in[3];
    const int*   e_v            = (const int*)  d_in[4];
    const float* W_left   = (const float*)d_in[5];
    const float* b_left   = (const float*)d_in[6];
    const float* W_edge   = (const float*)d_in[7];
    const float* W_right  = (const float*)d_in[8];
    const float* W_join   = (const float*)d_in[9];
    const float* b_join   = (const float*)d_in[10];
    const float* W_merge  = (const float*)d_in[11];
    const float* b_merge  = (const float*)d_in[12];
    const float* g_var    = (const float*)d_in[13];
    const float* b_var    = (const float*)d_in[14];
    const float* g_edge   = (const float*)d_in[15];
    const float* b_edge   = (const float*)d_in[16];
    const float* g_con    = (const float*)d_in[17];
    const float* b_con    = (const float*)d_in[18];
    const float* g_join_ln  = (const float*)d_in[19];
    const float* b_join_ln  = (const float*)d_in[20];
    const float* g_joint    = (const float*)d_in[21];
    const float* b_joint    = (const float*)d_in[22];
    const float* g_merge    = (const float*)d_in[23];
    const float* b_merge_ln = (const float*)d_in[24];

    float* out_var = (float*)d_out;
    float* out_con = (float*)d_out + (size_t)NUv * EMB;

    float *vt, *et, *ct, *agg;
    cudaGetSymbolAddress((void**)&vt,  g_vt);
    cudaGetSymbolAddress((void**)&et,  g_et);
    cudaGetSymbolAddress((void**)&ct,  g_ct);
    cudaGetSymbolAddress((void**)&agg, g_agg);

    const int SM_MMA   = (64 * WP_STRIDE + 64 * XS_STRIDE) * 4;        // 101,376 B
    const int SM_MERGE = (2 * EMB * EMB + 64 * 256) * sizeof(float);   // 192 KB

    cudaFuncSetAttribute(ln_gemm_tf32,   cudaFuncAttributeMaxDynamicSharedMemorySize, SM_MMA);
    cudaFuncSetAttribute(edge_join_tf32, cudaFuncAttributeMaxDynamicSharedMemorySize, SM_MMA);
    cudaFuncSetAttribute(merge_kernel,   cudaFuncAttributeMaxDynamicSharedMemorySize, SM_MERGE);

    const dim3 blk(256);

    // shared pre-transforms (vt and et identical in both passes)
    ln_gemm_tf32<<<GRID_MMA, blk, SM_MMA>>>(variable_emb, W_left, b_left, g_var, b_var, vt, NUv);
    ln_gemm_tf32<<<GRID_MMA, blk, SM_MMA>>>(edge_emb, W_edge, nullptr, g_edge, b_edge, et, NEv);
    ln_gemm_tf32<<<GRID_MMA, blk, SM_MMA>>>(constraint_emb, W_right, nullptr, g_con, b_con, ct, NVv);

    // ---------------- pass 1: var -> con ----------------
    cudaMemsetAsync(agg, 0, (size_t)NVv * EMB * sizeof(float), 0);
    edge_join_tf32<<<GRID_MMA, blk, SM_MMA>>>(vt, et, ct, e_u, e_v, W_join, b_join,
                                              g_join_ln, b_join_ln, g_joint, b_joint,
                                              agg, /*seg_by_ev=*/1, NEv);
    merge_kernel<<<GRID_MERGE, blk, SM_MERGE>>>(ct, agg, W_merge, b_merge, g_merge, b_merge_ln,
                                                out_con, NVv);

    // ---------------- pass 2: con -> var ----------------
    ln_gemm_tf32<<<GRID_MMA, blk, SM_MMA>>>(out_con, W_right, nullptr, g_con, b_con, ct, NVv);
    cudaMemsetAsync(agg, 0, (size_t)NUv * EMB * sizeof(float), 0);
    edge_join_tf32<<<GRID_MMA, blk, SM_MMA>>>(vt, et, ct, e_u, e_v, W_join, b_join,
                                              g_join_ln, b_join_ln, g_joint, b_joint,
                                              agg, /*seg_by_ev=*/0, NEv);
    merge_kernel<<<GRID_MERGE, blk, SM_MERGE>>>(vt, agg, W_merge, b_merge, g_merge, b_merge_ln,
                                                out_var, NUv);
}

// round 9
// speedup vs baseline: 2.4625x; 1.1137x over previous
#include <cuda_runtime.h>
#include <cuda_bf16.h>
#include <math.h>
#include <stdint.h>

#define EMB   128
#define NUv   100000
#define NVv   50000
#define NEv   500000

#define WP_STRIDE  264  // words per (kt,tig) W pair-row (paired b0,b1) -> LDS.64 B-frags
#define XS_STRIDE  132  // words per X row (K=128) -> conflict-free A-frag LDS
#define XS2_STRIDE 260  // words per X row (K=256) for merge

#define GRID_MMA   296  // 2 blocks/SM * 148 SMs (persistent-tile)
#define GRID_MERGE 148  // 1 block/SM (202KB smem)

// ---------------- scratch (device globals: allocation-guard-safe) ----------
__device__ float g_vt[(size_t)NUv * EMB];
__device__ float g_et[(size_t)NEv * EMB];
__device__ float g_ct[(size_t)NVv * EMB];
__device__ float g_agg[(size_t)NUv * EMB];

// ---------------- tf32 helpers ----------------
__device__ __forceinline__ uint32_t f2tf(float x) {
    uint32_t r;
    asm("cvt.rna.tf32.f32 %0, %1;" : "=r"(r) : "f"(x));
    return r;
}

__device__ __forceinline__ void mma8(float& c0, float& c1, float& c2, float& c3,
                                     uint32_t a0, uint32_t a1, uint32_t a2, uint32_t a3,
                                     uint32_t b0, uint32_t b1)
{
    asm volatile(
        "mma.sync.aligned.m16n8k8.row.col.f32.tf32.tf32.f32 "
        "{%0,%1,%2,%3}, {%4,%5,%6,%7}, {%8,%9}, {%0,%1,%2,%3};"
        : "+f"(c0), "+f"(c1), "+f"(c2), "+f"(c3)
        : "r"(a0), "r"(a1), "r"(a2), "r"(a3), "r"(b0), "r"(b1));
}

__device__ __forceinline__ void red_v4(float* p, float v0, float v1, float v2, float v3)
{
    asm volatile("red.global.add.v4.f32 [%0], {%1,%2,%3,%4};"
                 :: "l"(p), "f"(v0), "f"(v1), "f"(v2), "f"(v3) : "memory");
}

// Vectorized staging of W[KD][128] ([k][n]) into paired-tf32 smem:
//   Wp[(kt*4+tig)*WP_STRIDE + 2*n + half], k = kt*8 + half*4 + tig
template<int KD>
__device__ __forceinline__ void stage_W_tf32(const float* __restrict__ W,
                                             uint32_t* __restrict__ Wp,
                                             int tid, int nthreads)
{
    #pragma unroll 2
    for (int i = tid; i < (KD / 2) * 32; i += nthreads) {
        const int pr = i >> 5;
        const int c4 = i & 31;
        const int kt = pr >> 2, tig = pr & 3;
        const int k0 = kt * 8 + tig;
        const float4 w0 = ((const float4*)(W + (size_t)k0 * EMB))[c4];
        const float4 w1 = ((const float4*)(W + (size_t)(k0 + 4) * EMB))[c4];
        uint32_t* dst = Wp + pr * WP_STRIDE + 8 * c4;
        uint4 lo, hi;
        lo.x = f2tf(w0.x); lo.y = f2tf(w1.x); lo.z = f2tf(w0.y); lo.w = f2tf(w1.y);
        hi.x = f2tf(w0.z); hi.y = f2tf(w1.z); hi.z = f2tf(w0.w); hi.w = f2tf(w1.w);
        ((uint4*)dst)[0] = lo;
        ((uint4*)dst)[1] = hi;
    }
}

// Warp mainloop over HALF the N dim: rows [r0, r0+16), cols [ch*64, ch*64+64)
template<int NKT, int XSTR>
__device__ __forceinline__ void mma_mainloop_half(const uint32_t* __restrict__ Xs,
                                                  const uint32_t* __restrict__ Wp,
                                                  int r0, int gq, int tig, int ch,
                                                  float acc[8][4])
{
    #pragma unroll
    for (int kt = 0; kt < NKT; ++kt) {
        const uint32_t* xl = Xs + (r0 + gq) * XSTR + kt * 8;
        const uint32_t* xh = Xs + (r0 + gq + 8) * XSTR + kt * 8;
        const uint32_t a0 = xl[tig];
        const uint32_t a1 = xh[tig];
        const uint32_t a2 = xl[tig + 4];
        const uint32_t a3 = xh[tig + 4];
        const uint32_t* wrow = Wp + (kt * 4 + tig) * WP_STRIDE + 2 * (ch * 64);
        uint2 b[8];
        #pragma unroll
        for (int nt = 0; nt < 8; ++nt)
            b[nt] = *(const uint2*)(wrow + 2 * (nt * 8 + gq));
        #pragma unroll
        for (int nt = 0; nt < 8; ++nt)
            mma8(acc[nt][0], acc[nt][1], acc[nt][2], acc[nt][3],
                 a0, a1, a2, a3, b[nt].x, b[nt].y);
    }
}

// =====================================================================
// Kernel 1 (tf32, persistent): Y[row] = LN(X[row]; g,b) @ W (+bias)
// =====================================================================
__global__ __launch_bounds__(256, 2)
void ln_gemm_tf32(const float* __restrict__ X, const float* __restrict__ W,
                  const float* __restrict__ bias,
                  const float* __restrict__ g, const float* __restrict__ b,
                  float* __restrict__ Y, int N)
{
    extern __shared__ uint32_t smu[];
    uint32_t* Wp = smu;
    uint32_t* Xs = smu + 64 * WP_STRIDE;
    float*    Xf = (float*)Xs;

    const int tid  = threadIdx.x;
    const int lane = tid & 31;
    const int warp = tid >> 5;
    const int gq   = lane >> 2;
    const int tig  = lane & 3;
    const int r0   = (warp >> 1) * 16;
    const int ch   = warp & 1;

    stage_W_tf32<128>(W, Wp, tid, 256);

    const float4 gv = ((const float4*)g)[lane];
    const float4 bv = ((const float4*)b)[lane];
    float4 bb = make_float4(0.f, 0.f, 0.f, 0.f);
    if (bias) bb = ((const float4*)bias)[lane];

    const int nTiles = (N + 63) >> 6;
    for (int tile = blockIdx.x; tile < nTiles; tile += gridDim.x) {
        const int row0 = tile * 64;
        __syncthreads();

        #pragma unroll
        for (int r = 0; r < 8; ++r) {
            const int lr  = warp * 8 + r;
            const int row = row0 + lr;
            float4 xv = make_float4(0.f, 0.f, 0.f, 0.f);
            if (row < N) xv = ((const float4*)(X + (size_t)row * EMB))[lane];
            float s  = xv.x + xv.y + xv.z + xv.w;
            float ss = xv.x * xv.x + xv.y * xv.y + xv.z * xv.z + xv.w * xv.w;
            #pragma unroll
            for (int o = 16; o; o >>= 1) {
                s  += __shfl_xor_sync(0xffffffffu, s,  o);
                ss += __shfl_xor_sync(0xffffffffu, ss, o);
            }
            const float mu   = s * (1.f / EMB);
            const float rstd = rsqrtf(ss * (1.f / EMB) - mu * mu + 1e-5f);
            uint4 q;
            q.x = f2tf((xv.x - mu) * rstd * gv.x + bv.x);
            q.y = f2tf((xv.y - mu) * rstd * gv.y + bv.y);
            q.z = f2tf((xv.z - mu) * rstd * gv.z + bv.z);
            q.w = f2tf((xv.w - mu) * rstd * gv.w + bv.w);
            *(uint4*)(Xs + lr * XS_STRIDE + lane * 4) = q;
        }
        __syncthreads();

        float acc[8][4];
        #pragma unroll
        for (int i = 0; i < 8; ++i)
            #pragma unroll
            for (int j = 0; j < 4; ++j) acc[i][j] = 0.f;

        mma_mainloop_half<16, XS_STRIDE>(Xs, Wp, r0, gq, tig, ch, acc);

        __syncthreads();
        #pragma unroll
        for (int nt = 0; nt < 8; ++nt) {
            const int col = ch * 64 + nt * 8 + 2 * tig;
            float* rl = Xf + (r0 + gq)     * XS_STRIDE + col;
            float* rh = Xf + (r0 + gq + 8) * XS_STRIDE + col;
            rl[0] = acc[nt][0]; rl[1] = acc[nt][1];
            rh[0] = acc[nt][2]; rh[1] = acc[nt][3];
        }
        __syncthreads();

        #pragma unroll
        for (int r = 0; r < 8; ++r) {
            const int lr  = warp * 8 + r;
            const int row = row0 + lr;
            if (row < N) {
                float4 o = ((const float4*)(Xf + lr * XS_STRIDE))[lane];
                o.x += bb.x; o.y += bb.y; o.z += bb.z; o.w += bb.w;
                ((float4*)(Y + (size_t)row * EMB))[lane] = o;
            }
        }
    }
}

// =====================================================================
// Kernel 2 (tf32, persistent): fused edge join + LN + GEMM + LN + red.v4
// =====================================================================
__global__ __launch_bounds__(256, 2)
void edge_join_tf32(const float* __restrict__ vt, const float* __restrict__ et,
                    const float* __restrict__ ct,
                    const int* __restrict__ e_u, const int* __restrict__ e_v,
                    const float* __restrict__ Wj, const float* __restrict__ bj,
                    const float* __restrict__ g1, const float* __restrict__ b1,
                    const float* __restrict__ g2, const float* __restrict__ b2,
                    float* __restrict__ agg, int seg_by_ev, int NE)
{
    extern __shared__ uint32_t smu[];
    uint32_t* Wp = smu;
    uint32_t* Xs = smu + 64 * WP_STRIDE;
    __shared__ int   segs[64];
    __shared__ float sP[64][2], ssP[64][2];

    const int tid  = threadIdx.x;
    const int lane = tid & 31;
    const int warp = tid >> 5;
    const int gq   = lane >> 2;
    const int tig  = lane & 3;
    const int r0   = (warp >> 1) * 16;
    const int ch   = warp & 1;
    const bool odd = (tig & 1);

    stage_W_tf32<128>(Wj, Wp, tid, 256);

    const float4 g1v = ((const float4*)g1)[lane];
    const float4 b1v = ((const float4*)b1)[lane];

    const int nTiles = (NE + 63) >> 6;
    for (int tile = blockIdx.x; tile < nTiles; tile += gridDim.x) {
        const int e0 = tile * 64;
        __syncthreads();

        int iu[8], iv[8];
        #pragma unroll
        for (int r = 0; r < 8; ++r) {
            const int e = e0 + warp * 8 + r;
            iu[r] = (e < NE) ? __ldg(e_u + e) : -1;
            iv[r] = (e < NE) ? __ldg(e_v + e) : -1;
        }
        if (lane == 0) {
            #pragma unroll
            for (int r = 0; r < 8; ++r)
                segs[warp * 8 + r] = (iu[r] < 0) ? -1 : (seg_by_ev ? iv[r] : iu[r]);
        }

        #pragma unroll
        for (int r = 0; r < 8; ++r) {
            const int lr = warp * 8 + r;
            const int e  = e0 + lr;
            float4 xv = make_float4(0.f, 0.f, 0.f, 0.f);
            if (iu[r] >= 0) {
                const float4 a = ((const float4*)(vt + (size_t)iu[r] * EMB))[lane];
                const float4 m = ((const float4*)(et + (size_t)e     * EMB))[lane];
                const float4 c = ((const float4*)(ct + (size_t)iv[r] * EMB))[lane];
                xv.x = fmaxf(a.x + m.x + c.x, 0.f);
                xv.y = fmaxf(a.y + m.y + c.y, 0.f);
                xv.z = fmaxf(a.z + m.z + c.z, 0.f);
                xv.w = fmaxf(a.w + m.w + c.w, 0.f);
            }
            float s  = xv.x + xv.y + xv.z + xv.w;
            float ss = xv.x * xv.x + xv.y * xv.y + xv.z * xv.z + xv.w * xv.w;
            #pragma unroll
            for (int o = 16; o; o >>= 1) {
                s  += __shfl_xor_sync(0xffffffffu, s,  o);
                ss += __shfl_xor_sync(0xffffffffu, ss, o);
            }
            const float mu   = s * (1.f / EMB);
            const float rstd = rsqrtf(ss * (1.f / EMB) - mu * mu + 1e-5f);
            uint4 q;
            q.x = f2tf((xv.x - mu) * rstd * g1v.x + b1v.x);
            q.y = f2tf((xv.y - mu) * rstd * g1v.y + b1v.y);
            q.z = f2tf((xv.z - mu) * rstd * g1v.z + b1v.z);
            q.w = f2tf((xv.w - mu) * rstd * g1v.w + b1v.w);
            *(uint4*)(Xs + lr * XS_STRIDE + lane * 4) = q;
        }
        __syncthreads();

        float acc[8][4];
        #pragma unroll
        for (int i = 0; i < 8; ++i)
            #pragma unroll
            for (int j = 0; j < 4; ++j) acc[i][j] = 0.f;

        mma_mainloop_half<16, XS_STRIDE>(Xs, Wp, r0, gq, tig, ch, acc);

        // epilogue: +bias, cross-warp LN stats
        float s_lo = 0.f, ss_lo = 0.f, s_hi = 0.f, ss_hi = 0.f;
        #pragma unroll
        for (int nt = 0; nt < 8; ++nt) {
            const int col = ch * 64 + nt * 8 + 2 * tig;
            const float2 bjv = *(const float2*)(bj + col);
            acc[nt][0] += bjv.x; acc[nt][1] += bjv.y;
            acc[nt][2] += bjv.x; acc[nt][3] += bjv.y;
            s_lo  += acc[nt][0] + acc[nt][1];
            ss_lo += acc[nt][0] * acc[nt][0] + acc[nt][1] * acc[nt][1];
            s_hi  += acc[nt][2] + acc[nt][3];
            ss_hi += acc[nt][2] * acc[nt][2] + acc[nt][3] * acc[nt][3];
        }
        #pragma unroll
        for (int o = 1; o < 4; o <<= 1) {
            s_lo  += __shfl_xor_sync(0xffffffffu, s_lo,  o);
            ss_lo += __shfl_xor_sync(0xffffffffu, ss_lo, o);
            s_hi  += __shfl_xor_sync(0xffffffffu, s_hi,  o);
            ss_hi += __shfl_xor_sync(0xffffffffu, ss_hi, o);
        }
        if (tig == 0) {
            sP [r0 + gq][ch]     = s_lo;  ssP[r0 + gq][ch]     = ss_lo;
            sP [r0 + gq + 8][ch] = s_hi;  ssP[r0 + gq + 8][ch] = ss_hi;
        }
        __syncthreads();

        const float st_lo  = sP [r0 + gq][0]     + sP [r0 + gq][1];
        const float sst_lo = ssP[r0 + gq][0]     + ssP[r0 + gq][1];
        const float st_hi  = sP [r0 + gq + 8][0] + sP [r0 + gq + 8][1];
        const float sst_hi = ssP[r0 + gq + 8][0] + ssP[r0 + gq + 8][1];
        const float mu_lo   = st_lo * (1.f / EMB);
        const float rstd_lo = rsqrtf(sst_lo * (1.f / EMB) - mu_lo * mu_lo + 1e-5f);
        const float mu_hi   = st_hi * (1.f / EMB);
        const float rstd_hi = rsqrtf(sst_hi * (1.f / EMB) - mu_hi * mu_hi + 1e-5f);

        const int  seg_lo = segs[r0 + gq];
        const int  seg_hi = segs[r0 + gq + 8];
        const float mu    = odd ? mu_hi   : mu_lo;
        const float rstd  = odd ? rstd_hi : rstd_lo;
        const int   seg   = odd ? seg_hi  : seg_lo;
        float* base = agg + (size_t)(seg < 0 ? 0 : seg) * EMB;

        #pragma unroll
        for (int nt = 0; nt < 8; ++nt) {
            const float l0 = acc[nt][0], l1 = acc[nt][1];
            const float h0 = acc[nt][2], h1 = acc[nt][3];
            const float p0 = __shfl_xor_sync(0xffffffffu, odd ? l0 : h0, 1);
            const float p1 = __shfl_xor_sync(0xffffffffu, odd ? l1 : h1, 1);
            float v0, v1, v2, v3;
            if (!odd) { v0 = l0; v1 = l1; v2 = p0; v3 = p1; }
            else      { v0 = p0; v1 = p1; v2 = h0; v3 = h1; }
            const int col = ch * 64 + nt * 8 + (tig >> 1) * 4;
            const float4 gg  = *(const float4*)(g2 + col);
            const float4 b2v = *(const float4*)(b2 + col);
            v0 = (v0 - mu) * rstd * gg.x + b2v.x;
            v1 = (v1 - mu) * rstd * gg.y + b2v.y;
            v2 = (v2 - mu) * rstd * gg.z + b2v.z;
            v3 = (v3 - mu) * rstd * gg.w + b2v.w;
            if (seg >= 0) red_v4(base + col, v0, v1, v2, v3);
        }
    }
}

// =====================================================================
// Kernel 3 (tf32, persistent): merge
//   out = LN(relu(concat([h, agg]) @ Wm + bm); gm, bmln); dst = h + out
// Wp: 128 pair-rows (K=256). Xs: 64 x 260 (h in cols 0..127, agg 128..255;
// normalized output repacked into cols 128..255).
// =====================================================================
__global__ __launch_bounds__(256, 1)
void merge_tf32(const float* __restrict__ h, const float* __restrict__ agg,
                const float* __restrict__ Wm, const float* __restrict__ bm,
                const float* __restrict__ gm, const float* __restrict__ bmln,
                float* __restrict__ dst, int N)
{
    extern __shared__ uint32_t smu[];
    uint32_t* Wp = smu;                        // 128*264 words = 135168 B
    uint32_t* Xs = smu + 128 * WP_STRIDE;      // 64*260 words  = 66560 B
    float*    Xf = (float*)Xs;
    __shared__ float sP[64][2], ssP[64][2];

    const int tid  = threadIdx.x;
    const int lane = tid & 31;
    const int warp = tid >> 5;
    const int gq   = lane >> 2;
    const int tig  = lane & 3;
    const int r0   = (warp >> 1) * 16;
    const int ch   = warp & 1;

    stage_W_tf32<256>(Wm, Wp, tid, 256);

    const int nTiles = (N + 63) >> 6;
    for (int tile = blockIdx.x; tile < nTiles; tile += gridDim.x) {
        const int row0 = tile * 64;
        __syncthreads();

        // stage h (cols 0..127) and agg (cols 128..255), tf32-converted
        #pragma unroll
        for (int r = 0; r < 8; ++r) {
            const int lr  = warp * 8 + r;
            const int row = row0 + lr;
            float4 hv = make_float4(0.f, 0.f, 0.f, 0.f);
            float4 av = make_float4(0.f, 0.f, 0.f, 0.f);
            if (row < N) {
                hv = ((const float4*)(h   + (size_t)row * EMB))[lane];
                av = ((const float4*)(agg + (size_t)row * EMB))[lane];
            }
            uint4 qh, qa;
            qh.x = f2tf(hv.x); qh.y = f2tf(hv.y); qh.z = f2tf(hv.z); qh.w = f2tf(hv.w);
            qa.x = f2tf(av.x); qa.y = f2tf(av.y); qa.z = f2tf(av.z); qa.w = f2tf(av.w);
            *(uint4*)(Xs + lr * XS2_STRIDE + lane * 4)       = qh;
            *(uint4*)(Xs + lr * XS2_STRIDE + EMB + lane * 4) = qa;
        }
        __syncthreads();

        float acc[8][4];
        #pragma unroll
        for (int i = 0; i < 8; ++i)
            #pragma unroll
            for (int j = 0; j < 4; ++j) acc[i][j] = 0.f;

        mma_mainloop_half<32, XS2_STRIDE>(Xs, Wp, r0, gq, tig, ch, acc);

        // +bias, relu, cross-warp LN stats
        float s_lo = 0.f, ss_lo = 0.f, s_hi = 0.f, ss_hi = 0.f;
        #pragma unroll
        for (int nt = 0; nt < 8; ++nt) {
            const int col = ch * 64 + nt * 8 + 2 * tig;
            const float2 bmv = *(const float2*)(bm + col);
            acc[nt][0] = fmaxf(acc[nt][0] + bmv.x, 0.f);
            acc[nt][1] = fmaxf(acc[nt][1] + bmv.y, 0.f);
            acc[nt][2] = fmaxf(acc[nt][2] + bmv.x, 0.f);
            acc[nt][3] = fmaxf(acc[nt][3] + bmv.y, 0.f);
            s_lo  += acc[nt][0] + acc[nt][1];
            ss_lo += acc[nt][0] * acc[nt][0] + acc[nt][1] * acc[nt][1];
            s_hi  += acc[nt][2] + acc[nt][3];
            ss_hi += acc[nt][2] * acc[nt][2] + acc[nt][3] * acc[nt][3];
        }
        #pragma unroll
        for (int o = 1; o < 4; o <<= 1) {
            s_lo  += __shfl_xor_sync(0xffffffffu, s_lo,  o);
            ss_lo += __shfl_xor_sync(0xffffffffu, ss_lo, o);
            s_hi  += __shfl_xor_sync(0xffffffffu, s_hi,  o);
            ss_hi += __shfl_xor_sync(0xffffffffu, ss_hi, o);
        }
        if (tig == 0) {
            sP [r0 + gq][ch]     = s_lo;  ssP[r0 + gq][ch]     = ss_lo;
            sP [r0 + gq + 8][ch] = s_hi;  ssP[r0 + gq + 8][ch] = ss_hi;
        }
        __syncthreads();

        const float st_lo  = sP [r0 + gq][0]     + sP [r0 + gq][1];
        const float sst_lo = ssP[r0 + gq][0]     + ssP[r0 + gq][1];
        const float st_hi  = sP [r0 + gq + 8][0] + sP [r0 + gq + 8][1];
        const float sst_hi = ssP[r0 + gq + 8][0] + ssP[r0 + gq + 8][1];
        const float mu_lo   = st_lo * (1.f / EMB);
        const float rstd_lo = rsqrtf(sst_lo * (1.f / EMB) - mu_lo * mu_lo + 1e-5f);
        const float mu_hi   = st_hi * (1.f / EMB);
        const float rstd_hi = rsqrtf(sst_hi * (1.f / EMB) - mu_hi * mu_hi + 1e-5f);

        // normalize + repack into Xf cols 128..255
        #pragma unroll
        for (int nt = 0; nt < 8; ++nt) {
            const int col = ch * 64 + nt * 8 + 2 * tig;
            const float2 gg = *(const float2*)(gm + col);
            const float2 bb = *(const float2*)(bmln + col);
            float* rl = Xf + (r0 + gq)     * XS2_STRIDE + EMB + col;
            float* rh = Xf + (r0 + gq + 8) * XS2_STRIDE + EMB + col;
            rl[0] = (acc[nt][0] - mu_lo) * rstd_lo * gg.x + bb.x;
            rl[1] = (acc[nt][1] - mu_lo) * rstd_lo * gg.y + bb.y;
            rh[0] = (acc[nt][2] - mu_hi) * rstd_hi * gg.x + bb.x;
            rh[1] = (acc[nt][3] - mu_hi) * rstd_hi * gg.y + bb.y;
        }
        __syncthreads();

        // store: dst = exact f32 h (re-read, L2-hot) + out
        #pragma unroll
        for (int r = 0; r < 8; ++r) {
            const int lr  = warp * 8 + r;
            const int row = row0 + lr;
            if (row < N) {
                const float4 hv = ((const float4*)(h + (size_t)row * EMB))[lane];
                const float4 ov = ((const float4*)(Xf + lr * XS2_STRIDE + EMB))[lane];
                float4 o;
                o.x = hv.x + ov.x; o.y = hv.y + ov.y;
                o.z = hv.z + ov.z; o.w = hv.w + ov.w;
                ((float4*)(dst + (size_t)row * EMB))[lane] = o;
            }
        }
    }
}

// =====================================================================
// host
// =====================================================================
extern "C" void kernel_launch(void* const* d_in, const int* in_sizes, int n_in,
                              void* d_out, int out_size)
{
    const float* variable_emb   = (const float*)d_in[0];
    const float* edge_emb       = (const float*)d_in[1];
    const float* constraint_emb = (const float*)d_in[2];
    const int*   e_u            = (const int*)  d_in[3];
    const int*   e_v            = (const int*)  d_in[4];
    const float* W_left   = (const float*)d_in[5];
    const float* b_left   = (const float*)d_in[6];
    const float* W_edge   = (const float*)d_in[7];
    const float* W_right  = (const float*)d_in[8];
    const float* W_join   = (const float*)d_in[9];
    const float* b_join   = (const float*)d_in[10];
    const float* W_merge  = (const float*)d_in[11];
    const float* b_merge  = (const float*)d_in[12];
    const float* g_var    = (const float*)d_in[13];
    const float* b_var    = (const float*)d_in[14];
    const float* g_edge   = (const float*)d_in[15];
    const float* b_edge   = (const float*)d_in[16];
    const float* g_con    = (const float*)d_in[17];
    const float* b_con    = (const float*)d_in[18];
    const float* g_join_ln  = (const float*)d_in[19];
    const float* b_join_ln  = (const float*)d_in[20];
    const float* g_joint    = (const float*)d_in[21];
    const float* b_joint    = (const float*)d_in[22];
    const float* g_merge    = (const float*)d_in[23];
    const float* b_merge_ln = (const float*)d_in[24];

    float* out_var = (float*)d_out;
    float* out_con = (float*)d_out + (size_t)NUv * EMB;

    float *vt, *et, *ct, *agg;
    cudaGetSymbolAddress((void**)&vt,  g_vt);
    cudaGetSymbolAddress((void**)&et,  g_et);
    cudaGetSymbolAddress((void**)&ct,  g_ct);
    cudaGetSymbolAddress((void**)&agg, g_agg);

    const int SM_MMA   = (64 * WP_STRIDE + 64 * XS_STRIDE) * 4;          // 101,376 B
    const int SM_MERGE = (128 * WP_STRIDE + 64 * XS2_STRIDE) * 4;        // 201,728 B

    cudaFuncSetAttribute(ln_gemm_tf32,   cudaFuncAttributeMaxDynamicSharedMemorySize, SM_MMA);
    cudaFuncSetAttribute(edge_join_tf32, cudaFuncAttributeMaxDynamicSharedMemorySize, SM_MMA);
    cudaFuncSetAttribute(merge_tf32,     cudaFuncAttributeMaxDynamicSharedMemorySize, SM_MERGE);

    const dim3 blk(256);

    // shared pre-transforms (vt and et identical in both passes)
    ln_gemm_tf32<<<GRID_MMA, blk, SM_MMA>>>(variable_emb, W_left, b_left, g_var, b_var, vt, NUv);
    ln_gemm_tf32<<<GRID_MMA, blk, SM_MMA>>>(edge_emb, W_edge, nullptr, g_edge, b_edge, et, NEv);
    ln_gemm_tf32<<<GRID_MMA, blk, SM_MMA>>>(constraint_emb, W_right, nullptr, g_con, b_con, ct, NVv);

    // ---------------- pass 1: var -> con ----------------
    cudaMemsetAsync(agg, 0, (size_t)NVv * EMB * sizeof(float), 0);
    edge_join_tf32<<<GRID_MMA, blk, SM_MMA>>>(vt, et, ct, e_u, e_v, W_join, b_join,
                                              g_join_ln, b_join_ln, g_joint, b_joint,
                                              agg, /*seg_by_ev=*/1, NEv);
    merge_tf32<<<GRID_MERGE, blk, SM_MERGE>>>(ct, agg, W_merge, b_merge, g_merge, b_merge_ln,
                                              out_con, NVv);

    // ---------------- pass 2: con -> var ----------------
    ln_gemm_tf32<<<GRID_MMA, blk, SM_MMA>>>(out_con, W_right, nullptr, g_con, b_con, ct, NVv);
    cudaMemsetAsync(agg, 0, (size_t)NUv * EMB * sizeof(float), 0);
    edge_join_tf32<<<GRID_MMA, blk, SM_MMA>>>(vt, et, ct, e_u, e_v, W_join, b_join,
                                              g_join_ln, b_join_ln, g_joint, b_joint,
                                              agg, /*seg_by_ev=*/0, NEv);
    merge_tf32<<<GRID_MERGE, blk, SM_MERGE>>>(vt, agg, W_merge, b_merge, g_merge, b_merge_ln,
                                              out_var, NUv);
}

// round 11
// speedup vs baseline: 2.6267x; 1.0667x over previous
#include <cuda_runtime.h>
#include <cuda_bf16.h>
#include <math.h>
#include <stdint.h>

#define EMB   128
#define NUv   100000
#define NVv   50000
#define NEv   500000

#define WP_STRIDE  264  // words per (kt,tig) W pair-row (paired b0,b1) -> LDS.64 B-frags
#define XS_STRIDE  132  // words per X row (K=128) -> conflict-free A-frag LDS
#define XS2_STRIDE 260  // words per X row (K=256) for merge

#define GRID_MMA   296  // 2 blocks/SM * 148 SMs (persistent-tile)
#define GRID_MERGE 148

// ---------------- scratch (device globals: allocation-guard-safe) ----------
__device__ float g_vt[(size_t)NUv * EMB];
__device__ float g_et[(size_t)NEv * EMB];
__device__ float g_ct[(size_t)NVv * EMB];
__device__ float g_agg[(size_t)NUv * EMB];

// ---------------- tf32 helpers ----------------
__device__ __forceinline__ uint32_t f2tf(float x) {
    uint32_t r;
    asm("cvt.rna.tf32.f32 %0, %1;" : "=r"(r) : "f"(x));
    return r;
}

__device__ __forceinline__ void mma8(float& c0, float& c1, float& c2, float& c3,
                                     uint32_t a0, uint32_t a1, uint32_t a2, uint32_t a3,
                                     uint32_t b0, uint32_t b1)
{
    asm volatile(
        "mma.sync.aligned.m16n8k8.row.col.f32.tf32.tf32.f32 "
        "{%0,%1,%2,%3}, {%4,%5,%6,%7}, {%8,%9}, {%0,%1,%2,%3};"
        : "+f"(c0), "+f"(c1), "+f"(c2), "+f"(c3)
        : "r"(a0), "r"(a1), "r"(a2), "r"(a3), "r"(b0), "r"(b1));
}

__device__ __forceinline__ void red_v4(float* p, float v0, float v1, float v2, float v3)
{
    asm volatile("red.global.add.v4.f32 [%0], {%1,%2,%3,%4};"
                 :: "l"(p), "f"(v0), "f"(v1), "f"(v2), "f"(v3) : "memory");
}

// Vectorized staging of W[KD][128] ([k][n]) into paired-tf32 smem:
//   Wp[(kt*4+tig)*WP_STRIDE + 2*n + half], k = kt*8 + half*4 + tig
template<int KD>
__device__ __forceinline__ void stage_W_tf32(const float* __restrict__ W,
                                             uint32_t* __restrict__ Wp,
                                             int tid, int nthreads)
{
    #pragma unroll 2
    for (int i = tid; i < (KD / 2) * 32; i += nthreads) {
        const int pr = i >> 5;
        const int c4 = i & 31;
        const int kt = pr >> 2, tig = pr & 3;
        const int k0 = kt * 8 + tig;
        const float4 w0 = ((const float4*)(W + (size_t)k0 * EMB))[c4];
        const float4 w1 = ((const float4*)(W + (size_t)(k0 + 4) * EMB))[c4];
        uint32_t* dst = Wp + pr * WP_STRIDE + 8 * c4;
        uint4 lo, hi;
        lo.x = f2tf(w0.x); lo.y = f2tf(w1.x); lo.z = f2tf(w0.y); lo.w = f2tf(w1.y);
        hi.x = f2tf(w0.z); hi.y = f2tf(w1.z); hi.z = f2tf(w0.w); hi.w = f2tf(w1.w);
        ((uint4*)dst)[0] = lo;
        ((uint4*)dst)[1] = hi;
    }
}

// 16-row x 64-col warp mainloop (ln_gemm / merge)
template<int NKT, int XSTR>
__device__ __forceinline__ void mma_mainloop_half(const uint32_t* __restrict__ Xs,
                                                  const uint32_t* __restrict__ Wp,
                                                  int r0, int gq, int tig, int ch,
                                                  float acc[8][4])
{
    #pragma unroll
    for (int kt = 0; kt < NKT; ++kt) {
        const uint32_t* xl = Xs + (r0 + gq) * XSTR + kt * 8;
        const uint32_t* xh = Xs + (r0 + gq + 8) * XSTR + kt * 8;
        const uint32_t a0 = xl[tig];
        const uint32_t a1 = xh[tig];
        const uint32_t a2 = xl[tig + 4];
        const uint32_t a3 = xh[tig + 4];
        const uint32_t* wrow = Wp + (kt * 4 + tig) * WP_STRIDE + 2 * (ch * 64);
        uint2 bfr[8];
        #pragma unroll
        for (int nt = 0; nt < 8; ++nt)
            bfr[nt] = *(const uint2*)(wrow + 2 * (nt * 8 + gq));
        #pragma unroll
        for (int nt = 0; nt < 8; ++nt)
            mma8(acc[nt][0], acc[nt][1], acc[nt][2], acc[nt][3],
                 a0, a1, a2, a3, bfr[nt].x, bfr[nt].y);
    }
}

// =====================================================================
// Kernel 1 (tf32, persistent): Y[row] = LN(X[row]; g,b) @ W (+bias)
// X read is always a read-once stream -> __ldcs. stream_out: __stcs Y.
// =====================================================================
__global__ __launch_bounds__(256, 2)
void ln_gemm_tf32(const float* __restrict__ X, const float* __restrict__ W,
                  const float* __restrict__ bias,
                  const float* __restrict__ g, const float* __restrict__ b,
                  float* __restrict__ Y, int N, int stream_out)
{
    extern __shared__ uint32_t smu[];
    uint32_t* Wp = smu;
    uint32_t* Xs = smu + 64 * WP_STRIDE;
    float*    Xf = (float*)Xs;

    const int tid  = threadIdx.x;
    const int lane = tid & 31;
    const int warp = tid >> 5;
    const int gq   = lane >> 2;
    const int tig  = lane & 3;
    const int r0   = (warp >> 1) * 16;
    const int ch   = warp & 1;

    stage_W_tf32<128>(W, Wp, tid, 256);

    const float4 gv = ((const float4*)g)[lane];
    const float4 bv = ((const float4*)b)[lane];
    float4 bb = make_float4(0.f, 0.f, 0.f, 0.f);
    if (bias) bb = ((const float4*)bias)[lane];

    const int nTiles = (N + 63) >> 6;
    for (int tile = blockIdx.x; tile < nTiles; tile += gridDim.x) {
        const int row0 = tile * 64;
        __syncthreads();

        #pragma unroll
        for (int r = 0; r < 8; ++r) {
            const int lr  = warp * 8 + r;
            const int row = row0 + lr;
            float4 xv = make_float4(0.f, 0.f, 0.f, 0.f);
            if (row < N) xv = __ldcs(((const float4*)(X + (size_t)row * EMB)) + lane);
            float s  = xv.x + xv.y + xv.z + xv.w;
            float ss = xv.x * xv.x + xv.y * xv.y + xv.z * xv.z + xv.w * xv.w;
            #pragma unroll
            for (int o = 16; o; o >>= 1) {
                s  += __shfl_xor_sync(0xffffffffu, s,  o);
                ss += __shfl_xor_sync(0xffffffffu, ss, o);
            }
            const float mu   = s * (1.f / EMB);
            const float rstd = rsqrtf(ss * (1.f / EMB) - mu * mu + 1e-5f);
            uint4 q;
            q.x = f2tf((xv.x - mu) * rstd * gv.x + bv.x);
            q.y = f2tf((xv.y - mu) * rstd * gv.y + bv.y);
            q.z = f2tf((xv.z - mu) * rstd * gv.z + bv.z);
            q.w = f2tf((xv.w - mu) * rstd * gv.w + bv.w);
            *(uint4*)(Xs + lr * XS_STRIDE + lane * 4) = q;
        }
        __syncthreads();

        float acc[8][4];
        #pragma unroll
        for (int i = 0; i < 8; ++i)
            #pragma unroll
            for (int j = 0; j < 4; ++j) acc[i][j] = 0.f;

        mma_mainloop_half<16, XS_STRIDE>(Xs, Wp, r0, gq, tig, ch, acc);

        __syncthreads();
        #pragma unroll
        for (int nt = 0; nt < 8; ++nt) {
            const int col = ch * 64 + nt * 8 + 2 * tig;
            float* rl = Xf + (r0 + gq)     * XS_STRIDE + col;
            float* rh = Xf + (r0 + gq + 8) * XS_STRIDE + col;
            rl[0] = acc[nt][0]; rl[1] = acc[nt][1];
            rh[0] = acc[nt][2]; rh[1] = acc[nt][3];
        }
        __syncthreads();

        #pragma unroll
        for (int r = 0; r < 8; ++r) {
            const int lr  = warp * 8 + r;
            const int row = row0 + lr;
            if (row < N) {
                float4 o = ((const float4*)(Xf + lr * XS_STRIDE))[lane];
                o.x += bb.x; o.y += bb.y; o.z += bb.z; o.w += bb.w;
                if (stream_out) __stcs(((float4*)(Y + (size_t)row * EMB)) + lane, o);
                else            ((float4*)(Y + (size_t)row * EMB))[lane] = o;
            }
        }
    }
}

// =====================================================================
// Kernel 2 (tf32, persistent): fused edge join + LN + GEMM + LN + red.v4
// Warp tiling: 32 rows x 32 cols (2 rowgroups x 4 nt) -> B-frags reused
// across rowgroups (-20% mainloop LDS bytes). et loads are streaming.
// =====================================================================
__global__ __launch_bounds__(256, 2)
void edge_join_tf32(const float* __restrict__ vt, const float* __restrict__ et,
                    const float* __restrict__ ct,
                    const int* __restrict__ e_u, const int* __restrict__ e_v,
                    const float* __restrict__ Wj, const float* __restrict__ bj,
                    const float* __restrict__ g1, const float* __restrict__ b1,
                    const float* __restrict__ g2, const float* __restrict__ b2,
                    float* __restrict__ agg, int seg_by_ev, int NE)
{
    extern __shared__ uint32_t smu[];
    uint32_t* Wp = smu;
    uint32_t* Xs = smu + 64 * WP_STRIDE;
    __shared__ int   segs[64];
    __shared__ float sP[64][4], ssP[64][4];

    const int tid  = threadIdx.x;
    const int lane = tid & 31;
    const int warp = tid >> 5;
    const int gq   = lane >> 2;
    const int tig  = lane & 3;
    const int wr   = warp >> 2;        // 0-1: row half (32 rows)
    const int wc   = warp & 3;         // 0-3: col quarter (32 cols)
    const int rbase = wr * 32;
    const int cbase = wc * 32;
    const bool odd  = (tig & 1);

    stage_W_tf32<128>(Wj, Wp, tid, 256);

    const float4 g1v = ((const float4*)g1)[lane];
    const float4 b1v = ((const float4*)b1)[lane];

    const int nTiles = (NE + 63) >> 6;
    for (int tile = blockIdx.x; tile < nTiles; tile += gridDim.x) {
        const int e0 = tile * 64;
        __syncthreads();

        // ---- stage: warp stages rows warp*8..+8 ----
        int iu[8], iv[8];
        #pragma unroll
        for (int r = 0; r < 8; ++r) {
            const int e = e0 + warp * 8 + r;
            iu[r] = (e < NE) ? __ldg(e_u + e) : -1;
            iv[r] = (e < NE) ? __ldg(e_v + e) : -1;
        }
        if (lane == 0) {
            #pragma unroll
            for (int r = 0; r < 8; ++r)
                segs[warp * 8 + r] = (iu[r] < 0) ? -1 : (seg_by_ev ? iv[r] : iu[r]);
        }

        #pragma unroll
        for (int r = 0; r < 8; ++r) {
            const int lr = warp * 8 + r;
            const int e  = e0 + lr;
            float4 xv = make_float4(0.f, 0.f, 0.f, 0.f);
            if (iu[r] >= 0) {
                const float4 m = __ldcs(((const float4*)(et + (size_t)e * EMB)) + lane);
                const float4 a = ((const float4*)(vt + (size_t)iu[r] * EMB))[lane];
                const float4 c = ((const float4*)(ct + (size_t)iv[r] * EMB))[lane];
                xv.x = fmaxf(a.x + m.x + c.x, 0.f);
                xv.y = fmaxf(a.y + m.y + c.y, 0.f);
                xv.z = fmaxf(a.z + m.z + c.z, 0.f);
                xv.w = fmaxf(a.w + m.w + c.w, 0.f);
            }
            float s  = xv.x + xv.y + xv.z + xv.w;
            float ss = xv.x * xv.x + xv.y * xv.y + xv.z * xv.z + xv.w * xv.w;
            #pragma unroll
            for (int o = 16; o; o >>= 1) {
                s  += __shfl_xor_sync(0xffffffffu, s,  o);
                ss += __shfl_xor_sync(0xffffffffu, ss, o);
            }
            const float mu   = s * (1.f / EMB);
            const float rstd = rsqrtf(ss * (1.f / EMB) - mu * mu + 1e-5f);
            uint4 q;
            q.x = f2tf((xv.x - mu) * rstd * g1v.x + b1v.x);
            q.y = f2tf((xv.y - mu) * rstd * g1v.y + b1v.y);
            q.z = f2tf((xv.z - mu) * rstd * g1v.z + b1v.z);
            q.w = f2tf((xv.w - mu) * rstd * g1v.w + b1v.w);
            *(uint4*)(Xs + lr * XS_STRIDE + lane * 4) = q;
        }
        __syncthreads();

        // ---- mainloop: 2 rowgroups x 4 nt, B-frags shared across rowgroups
        float acc[2][4][4];
        #pragma unroll
        for (int rg = 0; rg < 2; ++rg)
            #pragma unroll
            for (int nt = 0; nt < 4; ++nt)
                #pragma unroll
                for (int j = 0; j < 4; ++j) acc[rg][nt][j] = 0.f;

        #pragma unroll
        for (int kt = 0; kt < 16; ++kt) {
            uint32_t a[2][4];
            #pragma unroll
            for (int rg = 0; rg < 2; ++rg) {
                const uint32_t* xl = Xs + (rbase + rg * 16 + gq) * XS_STRIDE + kt * 8;
                const uint32_t* xh = Xs + (rbase + rg * 16 + gq + 8) * XS_STRIDE + kt * 8;
                a[rg][0] = xl[tig];
                a[rg][1] = xh[tig];
                a[rg][2] = xl[tig + 4];
                a[rg][3] = xh[tig + 4];
            }
            const uint32_t* wrow = Wp + (kt * 4 + tig) * WP_STRIDE + 2 * cbase;
            uint2 bfr[4];
            #pragma unroll
            for (int nt = 0; nt < 4; ++nt)
                bfr[nt] = *(const uint2*)(wrow + 2 * (nt * 8 + gq));
            #pragma unroll
            for (int rg = 0; rg < 2; ++rg)
                #pragma unroll
                for (int nt = 0; nt < 4; ++nt)
                    mma8(acc[rg][nt][0], acc[rg][nt][1], acc[rg][nt][2], acc[rg][nt][3],
                         a[rg][0], a[rg][1], a[rg][2], a[rg][3], bfr[nt].x, bfr[nt].y);
        }

        // ---- epilogue: +bias, per-row partial stats (32-col partials) ----
        float sl[2] = {0.f, 0.f}, ssl[2] = {0.f, 0.f};
        float sh[2] = {0.f, 0.f}, ssh[2] = {0.f, 0.f};
        #pragma unroll
        for (int rg = 0; rg < 2; ++rg)
            #pragma unroll
            for (int nt = 0; nt < 4; ++nt) {
                const int col = cbase + nt * 8 + 2 * tig;
                const float2 bjv = *(const float2*)(bj + col);
                acc[rg][nt][0] += bjv.x; acc[rg][nt][1] += bjv.y;
                acc[rg][nt][2] += bjv.x; acc[rg][nt][3] += bjv.y;
                sl[rg]  += acc[rg][nt][0] + acc[rg][nt][1];
                ssl[rg] += acc[rg][nt][0] * acc[rg][nt][0] + acc[rg][nt][1] * acc[rg][nt][1];
                sh[rg]  += acc[rg][nt][2] + acc[rg][nt][3];
                ssh[rg] += acc[rg][nt][2] * acc[rg][nt][2] + acc[rg][nt][3] * acc[rg][nt][3];
            }
        #pragma unroll
        for (int o = 1; o < 4; o <<= 1) {
            #pragma unroll
            for (int rg = 0; rg < 2; ++rg) {
                sl[rg]  += __shfl_xor_sync(0xffffffffu, sl[rg],  o);
                ssl[rg] += __shfl_xor_sync(0xffffffffu, ssl[rg], o);
                sh[rg]  += __shfl_xor_sync(0xffffffffu, sh[rg],  o);
                ssh[rg] += __shfl_xor_sync(0xffffffffu, ssh[rg], o);
            }
        }
        if (tig == 0) {
            #pragma unroll
            for (int rg = 0; rg < 2; ++rg) {
                sP [rbase + rg * 16 + gq][wc]     = sl[rg];
                ssP[rbase + rg * 16 + gq][wc]     = ssl[rg];
                sP [rbase + rg * 16 + gq + 8][wc] = sh[rg];
                ssP[rbase + rg * 16 + gq + 8][wc] = ssh[rg];
            }
        }
        __syncthreads();

        // each thread scatters 2 rows (one per rowgroup), parity-selected
        #pragma unroll
        for (int rg = 0; rg < 2; ++rg) {
            const int row = rbase + rg * 16 + (odd ? gq + 8 : gq);
            const float4 sp  = *(const float4*)&sP [row][0];
            const float4 ssp = *(const float4*)&ssP[row][0];
            const float st  = sp.x + sp.y + sp.z + sp.w;
            const float sst = ssp.x + ssp.y + ssp.z + ssp.w;
            const float mu   = st * (1.f / EMB);
            const float rstd = rsqrtf(sst * (1.f / EMB) - mu * mu + 1e-5f);
            const int seg = segs[row];
            float* bse = agg + (size_t)(seg < 0 ? 0 : seg) * EMB;

            #pragma unroll
            for (int nt = 0; nt < 4; ++nt) {
                const float l0 = acc[rg][nt][0], l1 = acc[rg][nt][1];
                const float h0 = acc[rg][nt][2], h1 = acc[rg][nt][3];
                const float p0 = __shfl_xor_sync(0xffffffffu, odd ? l0 : h0, 1);
                const float p1 = __shfl_xor_sync(0xffffffffu, odd ? l1 : h1, 1);
                float v0, v1, v2, v3;
                if (!odd) { v0 = l0; v1 = l1; v2 = p0; v3 = p1; }
                else      { v0 = p0; v1 = p1; v2 = h0; v3 = h1; }
                const int col4 = cbase + nt * 8 + (tig >> 1) * 4;
                const float4 gg  = *(const float4*)(g2 + col4);
                const float4 b2v = *(const float4*)(b2 + col4);
                v0 = (v0 - mu) * rstd * gg.x + b2v.x;
                v1 = (v1 - mu) * rstd * gg.y + b2v.y;
                v2 = (v2 - mu) * rstd * gg.z + b2v.z;
                v3 = (v3 - mu) * rstd * gg.w + b2v.w;
                if (seg >= 0) red_v4(bse + col4, v0, v1, v2, v3);
            }
        }
    }
}

// =====================================================================
// merge (tf32, persistent)
// =====================================================================
__global__ __launch_bounds__(256, 1)
void merge_tf32(const float* __restrict__ h, const float* __restrict__ agg,
                const float* __restrict__ Wm, const float* __restrict__ bm,
                const float* __restrict__ gm, const float* __restrict__ bmln,
                float* __restrict__ dst, int N)
{
    extern __shared__ uint32_t smu[];
    uint32_t* Wp = smu;
    uint32_t* Xs = smu + 128 * WP_STRIDE;
    float*    Xf = (float*)Xs;
    __shared__ float sP[64][2], ssP[64][2];

    const int tid  = threadIdx.x;
    const int lane = tid & 31;
    const int warp = tid >> 5;
    const int gq   = lane >> 2;
    const int tig  = lane & 3;
    const int r0   = (warp >> 1) * 16;
    const int ch   = warp & 1;

    stage_W_tf32<256>(Wm, Wp, tid, 256);

    const int nTiles = (N + 63) >> 6;
    for (int tile = blockIdx.x; tile < nTiles; tile += gridDim.x) {
        const int row0 = tile * 64;
        __syncthreads();

        #pragma unroll
        for (int r = 0; r < 8; ++r) {
            const int lr  = warp * 8 + r;
            const int row = row0 + lr;
            float4 hv = make_float4(0.f, 0.f, 0.f, 0.f);
            float4 av = make_float4(0.f, 0.f, 0.f, 0.f);
            if (row < N) {
                hv = ((const float4*)(h + (size_t)row * EMB))[lane];
                av = __ldcs(((const float4*)(agg + (size_t)row * EMB)) + lane);
            }
            uint4 qh, qa;
            qh.x = f2tf(hv.x); qh.y = f2tf(hv.y); qh.z = f2tf(hv.z); qh.w = f2tf(hv.w);
            qa.x = f2tf(av.x); qa.y = f2tf(av.y); qa.z = f2tf(av.z); qa.w = f2tf(av.w);
            *(uint4*)(Xs + lr * XS2_STRIDE + lane * 4)       = qh;
            *(uint4*)(Xs + lr * XS2_STRIDE + EMB + lane * 4) = qa;
        }
        __syncthreads();

        float acc[8][4];
        #pragma unroll
        for (int i = 0; i < 8; ++i)
            #pragma unroll
            for (int j = 0; j < 4; ++j) acc[i][j] = 0.f;

        mma_mainloop_half<32, XS2_STRIDE>(Xs, Wp, r0, gq, tig, ch, acc);

        float s_lo = 0.f, ss_lo = 0.f, s_hi = 0.f, ss_hi = 0.f;
        #pragma unroll
        for (int nt = 0; nt < 8; ++nt) {
            const int col = ch * 64 + nt * 8 + 2 * tig;
            const float2 bmv = *(const float2*)(bm + col);
            acc[nt][0] = fmaxf(acc[nt][0] + bmv.x, 0.f);
            acc[nt][1] = fmaxf(acc[nt][1] + bmv.y, 0.f);
            acc[nt][2] = fmaxf(acc[nt][2] + bmv.x, 0.f);
            acc[nt][3] = fmaxf(acc[nt][3] + bmv.y, 0.f);
            s_lo  += acc[nt][0] + acc[nt][1];
            ss_lo += acc[nt][0] * acc[nt][0] + acc[nt][1] * acc[nt][1];
            s_hi  += acc[nt][2] + acc[nt][3];
            ss_hi += acc[nt][2] * acc[nt][2] + acc[nt][3] * acc[nt][3];
        }
        #pragma unroll
        for (int o = 1; o < 4; o <<= 1) {
            s_lo  += __shfl_xor_sync(0xffffffffu, s_lo,  o);
            ss_lo += __shfl_xor_sync(0xffffffffu, ss_lo, o);
            s_hi  += __shfl_xor_sync(0xffffffffu, s_hi,  o);
            ss_hi += __shfl_xor_sync(0xffffffffu, ss_hi, o);
        }
        if (tig == 0) {
            sP [r0 + gq][ch]     = s_lo;  ssP[r0 + gq][ch]     = ss_lo;
            sP [r0 + gq + 8][ch] = s_hi;  ssP[r0 + gq + 8][ch] = ss_hi;
        }
        __syncthreads();

        const float st_lo  = sP [r0 + gq][0]     + sP [r0 + gq][1];
        const float sst_lo = ssP[r0 + gq][0]     + ssP[r0 + gq][1];
        const float st_hi  = sP [r0 + gq + 8][0] + sP [r0 + gq + 8][1];
        const float sst_hi = ssP[r0 + gq + 8][0] + ssP[r0 + gq + 8][1];
        const float mu_lo   = st_lo * (1.f / EMB);
        const float rstd_lo = rsqrtf(sst_lo * (1.f / EMB) - mu_lo * mu_lo + 1e-5f);
        const float mu_hi   = st_hi * (1.f / EMB);
        const float rstd_hi = rsqrtf(sst_hi * (1.f / EMB) - mu_hi * mu_hi + 1e-5f);

        #pragma unroll
        for (int nt = 0; nt < 8; ++nt) {
            const int col = ch * 64 + nt * 8 + 2 * tig;
            const float2 gg = *(const float2*)(gm + col);
            const float2 bb = *(const float2*)(bmln + col);
            float* rl = Xf + (r0 + gq)     * XS2_STRIDE + EMB + col;
            float* rh = Xf + (r0 + gq + 8) * XS2_STRIDE + EMB + col;
            rl[0] = (acc[nt][0] - mu_lo) * rstd_lo * gg.x + bb.x;
            rl[1] = (acc[nt][1] - mu_lo) * rstd_lo * gg.y + bb.y;
            rh[0] = (acc[nt][2] - mu_hi) * rstd_hi * gg.x + bb.x;
            rh[1] = (acc[nt][3] - mu_hi) * rstd_hi * gg.y + bb.y;
        }
        __syncthreads();

        #pragma unroll
        for (int r = 0; r < 8; ++r) {
            const int lr  = warp * 8 + r;
            const int row = row0 + lr;
            if (row < N) {
                const float4 hv = ((const float4*)(h + (size_t)row * EMB))[lane];
                const float4 ov = ((const float4*)(Xf + lr * XS2_STRIDE + EMB))[lane];
                float4 o;
                o.x = hv.x + ov.x; o.y = hv.y + ov.y;
                o.z = hv.z + ov.z; o.w = hv.w + ov.w;
                ((float4*)(dst + (size_t)row * EMB))[lane] = o;
            }
        }
    }
}

// =====================================================================
// host
// =====================================================================
extern "C" void kernel_launch(void* const* d_in, const int* in_sizes, int n_in,
                              void* d_out, int out_size)
{
    const float* variable_emb   = (const float*)d_in[0];
    const float* edge_emb       = (const float*)d_in[1];
    const float* constraint_emb = (const float*)d_in[2];
    const int*   e_u            = (const int*)  d_in[3];
    const int*   e_v            = (const int*)  d_in[4];
    const float* W_left   = (const float*)d_in[5];
    const float* b_left   = (const float*)d_in[6];
    const float* W_edge   = (const float*)d_in[7];
    const float* W_right  = (const float*)d_in[8];
    const float* W_join   = (const float*)d_in[9];
    const float* b_join   = (const float*)d_in[10];
    const float* W_merge  = (const float*)d_in[11];
    const float* b_merge  = (const float*)d_in[12];
    const float* g_var    = (const float*)d_in[13];
    const float* b_var    = (const float*)d_in[14];
    const float* g_edge   = (const float*)d_in[15];
    const float* b_edge   = (const float*)d_in[16];
    const float* g_con    = (const float*)d_in[17];
    const float* b_con    = (const float*)d_in[18];
    const float* g_join_ln  = (const float*)d_in[19];
    const float* b_join_ln  = (const float*)d_in[20];
    const float* g_joint    = (const float*)d_in[21];
    const float* b_joint    = (const float*)d_in[22];
    const float* g_merge    = (const float*)d_in[23];
    const float* b_merge_ln = (const float*)d_in[24];

    float* out_var = (float*)d_out;
    float* out_con = (float*)d_out + (size_t)NUv * EMB;

    float *vt, *et, *ct, *agg;
    cudaGetSymbolAddress((void**)&vt,  g_vt);
    cudaGetSymbolAddress((void**)&et,  g_et);
    cudaGetSymbolAddress((void**)&ct,  g_ct);
    cudaGetSymbolAddress((void**)&agg, g_agg);

    const int SM_MMA   = (64 * WP_STRIDE + 64 * XS_STRIDE) * 4;
    const int SM_MERGE = (128 * WP_STRIDE + 64 * XS2_STRIDE) * 4;

    cudaFuncSetAttribute(ln_gemm_tf32,   cudaFuncAttributeMaxDynamicSharedMemorySize, SM_MMA);
    cudaFuncSetAttribute(edge_join_tf32, cudaFuncAttributeMaxDynamicSharedMemorySize, SM_MMA);
    cudaFuncSetAttribute(merge_tf32,     cudaFuncAttributeMaxDynamicSharedMemorySize, SM_MERGE);

    const dim3 blk(256);

    // shared pre-transforms (vt and et identical in both passes)
    ln_gemm_tf32<<<GRID_MMA, blk, SM_MMA>>>(variable_emb, W_left, b_left, g_var, b_var, vt, NUv, 0);
    ln_gemm_tf32<<<GRID_MMA, blk, SM_MMA>>>(edge_emb, W_edge, nullptr, g_edge, b_edge, et, NEv, 1);
    ln_gemm_tf32<<<GRID_MMA, blk, SM_MMA>>>(constraint_emb, W_right, nullptr, g_con, b_con, ct, NVv, 0);

    // ---------------- pass 1: var -> con ----------------
    cudaMemsetAsync(agg, 0, (size_t)NVv * EMB * sizeof(float), 0);
    edge_join_tf32<<<GRID_MMA, blk, SM_MMA>>>(vt, et, ct, e_u, e_v, W_join, b_join,
                                              g_join_ln, b_join_ln, g_joint, b_joint,
                                              agg, /*seg_by_ev=*/1, NEv);
    merge_tf32<<<GRID_MERGE, blk, SM_MERGE>>>(ct, agg, W_merge, b_merge, g_merge, b_merge_ln,
                                              out_con, NVv);

    // ---------------- pass 2: con -> var ----------------
    ln_gemm_tf32<<<GRID_MMA, blk, SM_MMA>>>(out_con, W_right, nullptr, g_con, b_con, ct, NVv, 0);
    cudaMemsetAsync(agg, 0, (size_t)NUv * EMB * sizeof(float), 0);
    edge_join_tf32<<<GRID_MMA, blk, SM_MMA>>>(vt, et, ct, e_u, e_v, W_join, b_join,
                                              g_join_ln, b_join_ln, g_joint, b_joint,
                                              agg, /*seg_by_ev=*/0, NEv);
    merge_tf32<<<GRID_MERGE, blk, SM_MERGE>>>(vt, agg, W_merge, b_merge, g_merge, b_merge_ln,
                                              out_var, NUv);
}